// round 8
// baseline (speedup 1.0000x reference)
#include <cuda_runtime.h>
#include <math.h>
#include <cstdint>
#include <mma.h>

using namespace nvcuda;

#define BSZ     4
#define LSEQ    4096
#define DMODEL  768
#define DSTATE  128
#define HEADDIM 64
#define DINNER  1536
#define NHEADS  24
#define DPROJ   3352       // logical in-proj width
#define DPROJP  3456       // padded to 27*128
#define CONVCH  1792       // 1536 + 2*128
#define EPSV    1e-5f
#define NBT     (BSZ*LSEQ) // 16384
#define TCH     32         // scan chunk

typedef unsigned long long u64;

// ---------------- scratch (static device globals) ---------------------------
__device__ float g_u   [(size_t)NBT * DMODEL];
__device__ float g_zx  [(size_t)NBT * DPROJP];
__device__ float g_xbc [(size_t)NBT * CONVCH];
__device__ float g_y   [(size_t)NBT * DINNER];
__device__ float g_dA  [NBT * NHEADS];
__device__ float g_dt  [NBT * NHEADS];
__device__ float g_win [(size_t)DMODEL * DPROJP];   // tf32, padded cols
__device__ float g_wout[(size_t)DINNER * DMODEL];   // tf32

// ---------------- helpers ----------------------------------------------------
__device__ __forceinline__ float to_tf32(float x) {
    float r; asm("cvt.rna.tf32.f32 %0, %1;" : "=f"(r) : "f"(x)); return r;
}
__device__ __forceinline__ u64 pk2(float lo, float hi) {
    u64 d; asm("mov.b64 %0, {%1, %2};" : "=l"(d) : "f"(lo), "f"(hi)); return d;
}
__device__ __forceinline__ void up2(u64 v, float& lo, float& hi) {
    asm("mov.b64 {%0, %1}, %2;" : "=f"(lo), "=f"(hi) : "l"(v));
}
__device__ __forceinline__ u64 ffma2(u64 a, u64 b, u64 c) {
    u64 d; asm("fma.rn.f32x2 %0, %1, %2, %3;" : "=l"(d) : "l"(a), "l"(b), "l"(c)); return d;
}
__device__ __forceinline__ u64 fmul2(u64 a, u64 b) {
    u64 d; asm("mul.rn.f32x2 %0, %1, %2;" : "=l"(d) : "l"(a), "l"(b)); return d;
}
__device__ __forceinline__ unsigned smem_u32(const void* p) {
    return (unsigned)__cvta_generic_to_shared(p);
}
#define CP16(dst, src)  asm volatile("cp.async.cg.shared.global [%0], [%1], 16;" :: "r"(dst), "l"(src))
#define CP_COMMIT()     asm volatile("cp.async.commit_group;")
#define CP_WAIT(n)      asm volatile("cp.async.wait_group %0;" :: "n"(n))

__device__ __forceinline__ float block_reduce_sum(float v, float* red) {
    #pragma unroll
    for (int o = 16; o; o >>= 1) v += __shfl_down_sync(0xffffffffu, v, o);
    int lane = threadIdx.x & 31, wid = threadIdx.x >> 5;
    if (lane == 0) red[wid] = v;
    __syncthreads();
    int nw = blockDim.x >> 5;
    v = (threadIdx.x < nw) ? red[threadIdx.x] : 0.f;
    if (wid == 0) {
        #pragma unroll
        for (int o = 16; o; o >>= 1) v += __shfl_down_sync(0xffffffffu, v, o);
        if (lane == 0) red[0] = v;
    }
    __syncthreads();
    return red[0];
}

// ---------------- profiling marker (no-op) -----------------------------------
__global__ void nop_kernel() {}

// ---------------- 0) weight convert/pad (tf32) -------------------------------
__global__ void cvt_win_kernel(const float* __restrict__ W) {
    int idx = blockIdx.x * 256 + threadIdx.x;
    if (idx >= DMODEL * DPROJP) return;
    int r = idx / DPROJP, c = idx % DPROJP;
    g_win[idx] = (c < DPROJ) ? to_tf32(W[(size_t)r * DPROJ + c]) : 0.f;
}
__global__ void cvt_wout_kernel(const float* __restrict__ W) {
    int idx = blockIdx.x * 256 + threadIdx.x;
    if (idx < DINNER * DMODEL) g_wout[idx] = to_tf32(W[idx]);
}

// ---------------- 1) LayerNorm (tf32-rounded output) -------------------------
__global__ void __launch_bounds__(256) ln_kernel(const float* __restrict__ x,
                                                 const float* __restrict__ w,
                                                 const float* __restrict__ b) {
    __shared__ float red[32];
    int row = blockIdx.x;
    const float* xr = x + (size_t)row * DMODEL;
    float v[3], s = 0.f, ss = 0.f;
    #pragma unroll
    for (int i = 0; i < 3; i++) {
        v[i] = xr[threadIdx.x + i * 256];
        s += v[i]; ss += v[i] * v[i];
    }
    float tot = block_reduce_sum(s, red);
    __syncthreads();
    float tot2 = block_reduce_sum(ss, red);
    float mu  = tot / DMODEL;
    float var = tot2 / DMODEL - mu * mu;
    float inv = rsqrtf(var + EPSV);
    float* ur = g_u + (size_t)row * DMODEL;
    #pragma unroll
    for (int i = 0; i < 3; i++) {
        int c = threadIdx.x + i * 256;
        ur[c] = to_tf32((v[i] - mu) * inv * w[c] + b[c]);
    }
}

// ---------------- TF32 wmma GEMM, 4-stage cp.async ring ----------------------
// 128x128 tile, BK=16, 4 stages, one __syncthreads per iteration.
// A [M,K] row-major (tf32-rounded fp32), B [K,N] row-major tf32 (padded so no
// guards needed). C stride NP. RESID: C = A*B + R.
#define GSTG 4
#define ASTR 20      // 16 + pad
#define BSTR 132     // 128 + pad
#define A_ELEM (128 * ASTR)            // 2560 floats per stage
#define B_ELEM (16 * BSTR)             // 2112 floats per stage
#define STG_ELEM (A_ELEM + B_ELEM)     // 4672
#define GEMM_SMEM (GSTG * STG_ELEM * 4)  // 74,752 B

template<bool RESID>
__global__ void __launch_bounds__(256) gemm_tf32(const float* __restrict__ A,
                                                 const float* __restrict__ B,
                                                 float* __restrict__ C,
                                                 const float* __restrict__ R,
                                                 int NP, int NB, int K) {
    extern __shared__ float smem[];
    float* As = smem;                       // [GSTG][128][ASTR]
    float* Bs = smem + GSTG * A_ELEM;       // [GSTG][16][BSTR]

    int tid  = threadIdx.x;
    int warp = tid >> 5, wm = warp >> 1, wn = warp & 1;
    int row0 = blockIdx.y * 128, col0 = blockIdx.x * 128;

    wmma::fragment<wmma::accumulator, 16, 16, 8, float> acc[2][4];
    #pragma unroll
    for (int i = 0; i < 2; i++)
        #pragma unroll
        for (int j = 0; j < 4; j++) wmma::fill_fragment(acc[i][j], 0.f);

    // per-thread load coords
    int a_r = tid >> 2, a_c = (tid & 3) * 4;          // + u*64 rows
    int b_r = tid >> 5, b_c = (tid & 31) * 4;         // + u*8 rows

    auto issue_stage = [&](int s, int k0) {
        float* Ad = As + s * A_ELEM;
        float* Bd = Bs + s * B_ELEM;
        #pragma unroll
        for (int u = 0; u < 2; u++) {
            int r = a_r + u * 64;
            CP16(smem_u32(Ad + r * ASTR + a_c),
                 A + (size_t)(row0 + r) * K + k0 + a_c);
        }
        #pragma unroll
        for (int u = 0; u < 2; u++) {
            int r = b_r + u * 8;
            CP16(smem_u32(Bd + r * BSTR + b_c),
                 B + (size_t)(k0 + r) * NB + col0 + b_c);
        }
    };

    int nk = K / 16;
    #pragma unroll
    for (int s = 0; s < GSTG - 1; s++) { issue_stage(s, s * 16); CP_COMMIT(); }

    for (int i = 0; i < nk; i++) {
        CP_WAIT(GSTG - 2);
        __syncthreads();
        // prefetch stage i+GSTG-1 (overwrites buffer consumed at iter i-1;
        // all threads are past that compute thanks to the barrier above)
        if (i + GSTG - 1 < nk) issue_stage((i + GSTG - 1) & (GSTG - 1), (i + GSTG - 1) * 16);
        CP_COMMIT();   // always commit: keeps group count aligned with wait(N)

        int s = i & (GSTG - 1);
        const float* Ap = As + s * A_ELEM;
        const float* Bp = Bs + s * B_ELEM;
        #pragma unroll
        for (int kk = 0; kk < 16; kk += 8) {
            wmma::fragment<wmma::matrix_a, 16, 16, 8, wmma::precision::tf32, wmma::row_major> af[2];
            wmma::fragment<wmma::matrix_b, 16, 16, 8, wmma::precision::tf32, wmma::row_major> bf[4];
            #pragma unroll
            for (int a = 0; a < 2; a++)
                wmma::load_matrix_sync(af[a], Ap + (wm * 32 + a * 16) * ASTR + kk, ASTR);
            #pragma unroll
            for (int b = 0; b < 4; b++)
                wmma::load_matrix_sync(bf[b], Bp + kk * BSTR + wn * 64 + b * 16, BSTR);
            #pragma unroll
            for (int a = 0; a < 2; a++)
                #pragma unroll
                for (int b = 0; b < 4; b++)
                    wmma::mma_sync(acc[a][b], af[a], bf[b], acc[a][b]);
        }
    }

    #pragma unroll
    for (int i = 0; i < 2; i++)
        #pragma unroll
        for (int j = 0; j < 4; j++) {
            int r = row0 + wm * 32 + i * 16;
            int c = col0 + wn * 64 + j * 16;
            float* Cp = C + (size_t)r * NP + c;
            if (RESID) {
                wmma::fragment<wmma::accumulator, 16, 16, 8, float> rf;
                wmma::load_matrix_sync(rf, R + (size_t)r * NP + c, NP, wmma::mem_row_major);
                #pragma unroll
                for (int e = 0; e < rf.num_elements; e++) acc[i][j].x[e] += rf.x[e];
            }
            wmma::store_matrix_sync(Cp, acc[i][j], NP, wmma::mem_row_major);
        }
}

// ---------------- 3) causal depthwise conv (K=4) + SiLU ----------------------
__global__ void conv_kernel(const float* __restrict__ cw, const float* __restrict__ cb) {
    int id = blockIdx.x * blockDim.x + threadIdx.x;
    if (id >= NBT * CONVCH) return;
    int c  = id % CONVCH;
    int bt = id / CONVCH;
    int t  = bt % LSEQ;
    int b  = bt / LSEQ;
    const float* src = g_zx + (size_t)(b * LSEQ) * DPROJP + DINNER + c;
    float acc = cb[c];
    #pragma unroll
    for (int k = 0; k < 4; k++) {
        int ti = t - 3 + k;
        if (ti >= 0) acc = fmaf(cw[c * 4 + k], src[(size_t)ti * DPROJP], acc);
    }
    g_xbc[id] = acc / (1.f + expf(-acc));   // SiLU
}

// ---------------- 4) dt softplus + dA ----------------------------------------
__global__ void dt_kernel(const float* __restrict__ dt_bias, const float* __restrict__ A_log) {
    int id = blockIdx.x * blockDim.x + threadIdx.x;
    if (id >= NBT * NHEADS) return;
    int h  = id % NHEADS;
    int bt = id / NHEADS;
    float v  = g_zx[(size_t)bt * DPROJP + (DINNER + DINNER + 2 * DSTATE) + h] + dt_bias[h];
    float sp = (v > 20.f) ? v : log1pf(expf(v));
    g_dt[id] = sp;
    g_dA[id] = expf(-expf(A_log[h]) * sp);
}

// ---------------- 5) selective scan: smem-staged chunks + f32x2 --------------
__global__ void __launch_bounds__(512) scan_kernel(const float* __restrict__ Dv) {
    __shared__ float sBC[TCH][256];
    __shared__ float sX [TCH][64];
    __shared__ float sdA[TCH];
    __shared__ float sdt[TCH];

    int blk = blockIdx.x;
    int b = blk / NHEADS, h = blk % NHEADS;
    int tid = threadIdx.x;
    int p = tid >> 3, sub = tid & 7, n0 = sub * 16;

    const float* base = g_xbc + (size_t)(b * LSEQ) * CONVCH;
    const float* dAb  = g_dA + (b * LSEQ) * NHEADS + h;
    const float* dtb  = g_dt + (b * LSEQ) * NHEADS + h;
    float Dh = Dv[h];
    float* yb = g_y + (size_t)(b * LSEQ) * DINNER + h * HEADDIM + p;

    u64 hs[8];
    #pragma unroll
    for (int i = 0; i < 8; i++) hs[i] = 0ull;

    for (int t0 = 0; t0 < LSEQ; t0 += TCH) {
        __syncthreads();
        #pragma unroll
        for (int i = 0; i < 4; i++) {
            int idx = tid + 512 * i;
            int r = idx >> 6, c = (idx & 63) * 4;
            *(float4*)&sBC[r][c] =
                *(const float4*)(base + (size_t)(t0 + r) * CONVCH + DINNER + c);
        }
        {
            int r = tid >> 4, c = (tid & 15) * 4;
            *(float4*)&sX[r][c] =
                *(const float4*)(base + (size_t)(t0 + r) * CONVCH + h * HEADDIM + c);
        }
        if (tid < TCH)            sdA[tid]       = dAb[(t0 + tid) * NHEADS];
        else if (tid < 2 * TCH)   sdt[tid - TCH] = dtb[(t0 + tid - TCH) * NHEADS];
        __syncthreads();

        for (int tt = 0; tt < TCH; tt++) {
            float cdA = sdA[tt], cdt = sdt[tt], cx = sX[tt][p];
            float dtx = cdt * cx;
            u64 cdA2 = pk2(cdA, cdA);
            u64 dtx2 = pk2(dtx, dtx);
            u64 acc2 = 0ull;
            #pragma unroll
            for (int i = 0; i < 4; i++) {
                float4 bv = *(const float4*)&sBC[tt][n0 + i * 4];
                float4 cv = *(const float4*)&sBC[tt][128 + n0 + i * 4];
                u64 b01 = pk2(bv.x, bv.y), b23 = pk2(bv.z, bv.w);
                u64 c01 = pk2(cv.x, cv.y), c23 = pk2(cv.z, cv.w);
                hs[i*2]   = ffma2(cdA2, hs[i*2],   fmul2(dtx2, b01));
                acc2      = ffma2(hs[i*2],   c01, acc2);
                hs[i*2+1] = ffma2(cdA2, hs[i*2+1], fmul2(dtx2, b23));
                acc2      = ffma2(hs[i*2+1], c23, acc2);
            }
            float ax, ay; up2(acc2, ax, ay);
            float acc = ax + ay;
            acc += __shfl_down_sync(0xffffffffu, acc, 4, 8);
            acc += __shfl_down_sync(0xffffffffu, acc, 2, 8);
            acc += __shfl_down_sync(0xffffffffu, acc, 1, 8);
            if (sub == 0) yb[(size_t)(t0 + tt) * DINNER] = acc + Dh * cx;
        }
    }
}

// ---------------- 6) gate (y * silu(z)) + RMSNorm (tf32-rounded) -------------
__global__ void __launch_bounds__(256) gate_kernel(const float* __restrict__ norm_w) {
    __shared__ float red[32];
    int row = blockIdx.x;
    const float* zr = g_zx + (size_t)row * DPROJP;
    float* yr = g_y + (size_t)row * DINNER;
    float g[6], ss = 0.f;
    #pragma unroll
    for (int i = 0; i < 6; i++) {
        int c = threadIdx.x + i * 256;
        float z = zr[c];
        float y = yr[c];
        float gv = y * (z / (1.f + expf(-z)));
        g[i] = gv;
        ss += gv * gv;
    }
    float tot = block_reduce_sum(ss, red);
    float inv = rsqrtf(tot / DINNER + EPSV);
    #pragma unroll
    for (int i = 0; i < 6; i++) {
        int c = threadIdx.x + i * 256;
        yr[c] = to_tf32(g[i] * inv * norm_w[c]);
    }
}

// ---------------- launcher ----------------------------------------------------
extern "C" void kernel_launch(void* const* d_in, const int* in_sizes, int n_in,
                              void* d_out, int out_size) {
    const float* x       = (const float*)d_in[0];
    const float* ln_w    = (const float*)d_in[1];
    const float* ln_b    = (const float*)d_in[2];
    const float* W_in    = (const float*)d_in[3];
    const float* conv_w  = (const float*)d_in[4];
    const float* conv_b  = (const float*)d_in[5];
    const float* A_log   = (const float*)d_in[6];
    const float* Dv      = (const float*)d_in[7];
    const float* dt_bias = (const float*)d_in[8];
    const float* norm_w  = (const float*)d_in[9];
    const float* W_out   = (const float*)d_in[10];
    float* out = (float*)d_out;

    float *pu, *pzx, *py, *pwin, *pwout;
    cudaGetSymbolAddress((void**)&pu,    g_u);
    cudaGetSymbolAddress((void**)&pzx,   g_zx);
    cudaGetSymbolAddress((void**)&py,    g_y);
    cudaGetSymbolAddress((void**)&pwin,  g_win);
    cudaGetSymbolAddress((void**)&pwout, g_wout);

    cudaFuncSetAttribute(gemm_tf32<false>, cudaFuncAttributeMaxDynamicSharedMemorySize, GEMM_SMEM);
    cudaFuncSetAttribute(gemm_tf32<true>,  cudaFuncAttributeMaxDynamicSharedMemorySize, GEMM_SMEM);

    cvt_win_kernel <<<(DMODEL * DPROJP + 255) / 256, 256>>>(W_in);     // launch 0
    cvt_wout_kernel<<<(DINNER * DMODEL + 255) / 256, 256>>>(W_out);    // launch 1

    ln_kernel<<<NBT, 256>>>(x, ln_w, ln_b);                            // launch 2

    nop_kernel<<<1, 1>>>();                                            // launch 3
    nop_kernel<<<1, 1>>>();                                            // launch 4

    // GEMM1 (launch 5 — ncu -s 5 lands here): [16384x768]@[768x3456]
    dim3 g1(DPROJP / 128, NBT / 128);   // 27 x 128
    gemm_tf32<false><<<g1, 256, GEMM_SMEM>>>(pu, pwin, pzx, nullptr,
                                             DPROJP, DPROJP, DMODEL);

    conv_kernel<<<(NBT * CONVCH + 255) / 256, 256>>>(conv_w, conv_b);
    dt_kernel<<<(NBT * NHEADS + 255) / 256, 256>>>(dt_bias, A_log);

    scan_kernel<<<BSZ * NHEADS, 512>>>(Dv);

    gate_kernel<<<NBT, 256>>>(norm_w);

    // GEMM2: [16384x1536] @ [1536x768] + x -> out
    dim3 g2(DMODEL / 128, NBT / 128);   // 6 x 128
    gemm_tf32<true><<<g2, 256, GEMM_SMEM>>>(py, pwout, out, x,
                                            DMODEL, DMODEL, DINNER);
}

// round 9
// speedup vs baseline: 1.3058x; 1.3058x over previous
#include <cuda_runtime.h>
#include <cuda_fp16.h>
#include <math.h>
#include <cstdint>
#include <mma.h>

using namespace nvcuda;

#define BSZ     4
#define LSEQ    4096
#define DMODEL  768
#define DSTATE  128
#define HEADDIM 64
#define DINNER  1536
#define NHEADS  24
#define DPROJ   3352       // logical in-proj width
#define DPROJP  3456       // padded to 27*128
#define CONVCH  1792       // 1536 + 2*128
#define EPSV    1e-5f
#define NBT     (BSZ*LSEQ) // 16384
#define TCH     32         // scan chunk

typedef unsigned long long u64;

// ---------------- scratch (static device globals) ---------------------------
__device__ __half g_uh   [(size_t)NBT * DMODEL];    // LN output, fp16
__device__ float  g_zx   [(size_t)NBT * DPROJP];    // GEMM1 out, fp32
__device__ float  g_xbc  [(size_t)NBT * CONVCH];
__device__ float  g_y    [(size_t)NBT * DINNER];    // scan out, fp32
__device__ __half g_yh   [(size_t)NBT * DINNER];    // gated+normed, fp16
__device__ float  g_dA   [NBT * NHEADS];
__device__ float  g_dt   [NBT * NHEADS];
__device__ __half g_winh [(size_t)DMODEL * DPROJP]; // fp16, padded cols
__device__ __half g_wouth[(size_t)DINNER * DMODEL]; // fp16

// ---------------- helpers ----------------------------------------------------
__device__ __forceinline__ u64 pk2(float lo, float hi) {
    u64 d; asm("mov.b64 %0, {%1, %2};" : "=l"(d) : "f"(lo), "f"(hi)); return d;
}
__device__ __forceinline__ void up2(u64 v, float& lo, float& hi) {
    asm("mov.b64 {%0, %1}, %2;" : "=f"(lo), "=f"(hi) : "l"(v));
}
__device__ __forceinline__ u64 ffma2(u64 a, u64 b, u64 c) {
    u64 d; asm("fma.rn.f32x2 %0, %1, %2, %3;" : "=l"(d) : "l"(a), "l"(b), "l"(c)); return d;
}
__device__ __forceinline__ u64 fmul2(u64 a, u64 b) {
    u64 d; asm("mul.rn.f32x2 %0, %1, %2;" : "=l"(d) : "l"(a), "l"(b)); return d;
}
__device__ __forceinline__ unsigned smem_u32(const void* p) {
    return (unsigned)__cvta_generic_to_shared(p);
}
#define CP16(dst, src)  asm volatile("cp.async.cg.shared.global [%0], [%1], 16;" :: "r"(dst), "l"(src))
#define CP_COMMIT()     asm volatile("cp.async.commit_group;")
#define CP_WAIT(n)      asm volatile("cp.async.wait_group %0;" :: "n"(n))

__device__ __forceinline__ float block_reduce_sum(float v, float* red) {
    #pragma unroll
    for (int o = 16; o; o >>= 1) v += __shfl_down_sync(0xffffffffu, v, o);
    int lane = threadIdx.x & 31, wid = threadIdx.x >> 5;
    if (lane == 0) red[wid] = v;
    __syncthreads();
    int nw = blockDim.x >> 5;
    v = (threadIdx.x < nw) ? red[threadIdx.x] : 0.f;
    if (wid == 0) {
        #pragma unroll
        for (int o = 16; o; o >>= 1) v += __shfl_down_sync(0xffffffffu, v, o);
        if (lane == 0) red[0] = v;
    }
    __syncthreads();
    return red[0];
}

// ---------------- 0) weight convert/pad (fp16) -------------------------------
__global__ void cvt_win_kernel(const float* __restrict__ W) {
    int idx = blockIdx.x * 256 + threadIdx.x;
    if (idx >= DMODEL * DPROJP) return;
    int r = idx / DPROJP, c = idx % DPROJP;
    g_winh[idx] = (c < DPROJ) ? __float2half_rn(W[(size_t)r * DPROJ + c])
                              : __half(0.f);
}
__global__ void cvt_wout_kernel(const float* __restrict__ W) {
    int idx = blockIdx.x * 256 + threadIdx.x;
    if (idx < DINNER * DMODEL) g_wouth[idx] = __float2half_rn(W[idx]);
}

// ---------------- 1) LayerNorm (fp16 output) ---------------------------------
__global__ void __launch_bounds__(256) ln_kernel(const float* __restrict__ x,
                                                 const float* __restrict__ w,
                                                 const float* __restrict__ b) {
    __shared__ float red[32];
    int row = blockIdx.x;
    const float* xr = x + (size_t)row * DMODEL;
    float v[3], s = 0.f, ss = 0.f;
    #pragma unroll
    for (int i = 0; i < 3; i++) {
        v[i] = xr[threadIdx.x + i * 256];
        s += v[i]; ss += v[i] * v[i];
    }
    float tot = block_reduce_sum(s, red);
    __syncthreads();
    float tot2 = block_reduce_sum(ss, red);
    float mu  = tot / DMODEL;
    float var = tot2 / DMODEL - mu * mu;
    float inv = rsqrtf(var + EPSV);
    __half* ur = g_uh + (size_t)row * DMODEL;
    #pragma unroll
    for (int i = 0; i < 3; i++) {
        int c = threadIdx.x + i * 256;
        ur[c] = __float2half_rn((v[i] - mu) * inv * w[c] + b[c]);
    }
}

// ---------------- FP16 wmma GEMM, 3-stage cp.async ring ----------------------
// 128x128 tile, BK=32, 3 stages, one __syncthreads per iteration.
// A [M,K] fp16 row-major, B [K,NB] fp16 row-major (padded: no guards).
// C fp32 stride NP. RESID: C = A*B + R.
#define GSTG 3
#define ASTRH 40     // 32 + 8 pad (halves)
#define BSTRH 136    // 128 + 8 pad
#define A_ELEMH (128 * ASTRH)           // 5120 halves / stage
#define B_ELEMH (32 * BSTRH)            // 4352 halves / stage
#define STG_ELEMH (A_ELEMH + B_ELEMH)
#define GEMM_SMEM (GSTG * STG_ELEMH * 2)   // 56,832 B

template<bool RESID>
__global__ void __launch_bounds__(256, 2)
gemm_fp16(const __half* __restrict__ A, const __half* __restrict__ B,
          float* __restrict__ C, const float* __restrict__ R,
          int NP, int NB, int K) {
    extern __shared__ __half hsm[];
    __half* As = hsm;                         // [GSTG][128][ASTRH]
    __half* Bs = hsm + GSTG * A_ELEMH;        // [GSTG][32][BSTRH]

    int tid  = threadIdx.x;
    int warp = tid >> 5, wm = warp >> 1, wn = warp & 1;
    int row0 = blockIdx.y * 128, col0 = blockIdx.x * 128;

    wmma::fragment<wmma::accumulator, 16, 16, 16, float> acc[2][4];
    #pragma unroll
    for (int i = 0; i < 2; i++)
        #pragma unroll
        for (int j = 0; j < 4; j++) wmma::fill_fragment(acc[i][j], 0.f);

    // A: 128 rows x 32 halves = 512 16B-chunks; 2/thread
    int a_r = tid >> 2, a_c = (tid & 3) * 8;
    // B: 32 rows x 128 halves = 512 chunks; 2/thread
    int b_r = tid >> 4, b_c = (tid & 15) * 8;

    auto issue_stage = [&](int s, int k0) {
        __half* Ad = As + s * A_ELEMH;
        __half* Bd = Bs + s * B_ELEMH;
        #pragma unroll
        for (int u = 0; u < 2; u++) {
            int r = a_r + u * 64;
            CP16(smem_u32(Ad + r * ASTRH + a_c),
                 A + (size_t)(row0 + r) * K + k0 + a_c);
        }
        #pragma unroll
        for (int u = 0; u < 2; u++) {
            int r = b_r + u * 16;
            CP16(smem_u32(Bd + r * BSTRH + b_c),
                 B + (size_t)(k0 + r) * NB + col0 + b_c);
        }
    };

    int nk = K / 32;
    issue_stage(0, 0);  CP_COMMIT();
    issue_stage(1, 32); CP_COMMIT();

    for (int i = 0; i < nk; i++) {
        CP_WAIT(1);           // stage i resident (≤1 group pending)
        __syncthreads();      // everyone done with stage read at iter i-1
        if (i + 2 < nk) issue_stage((i + 2) % GSTG, (i + 2) * 32);
        CP_COMMIT();          // keep group count aligned

        int s = i % GSTG;
        const __half* Ap = As + s * A_ELEMH;
        const __half* Bp = Bs + s * B_ELEMH;
        #pragma unroll
        for (int kk = 0; kk < 32; kk += 16) {
            wmma::fragment<wmma::matrix_a, 16, 16, 16, __half, wmma::row_major> af[2];
            #pragma unroll
            for (int a = 0; a < 2; a++)
                wmma::load_matrix_sync(af[a], Ap + (wm * 32 + a * 16) * ASTRH + kk, ASTRH);
            #pragma unroll
            for (int b = 0; b < 4; b++) {
                wmma::fragment<wmma::matrix_b, 16, 16, 16, __half, wmma::row_major> bf;
                wmma::load_matrix_sync(bf, Bp + kk * BSTRH + wn * 64 + b * 16, BSTRH);
                wmma::mma_sync(acc[0][b], af[0], bf, acc[0][b]);
                wmma::mma_sync(acc[1][b], af[1], bf, acc[1][b]);
            }
        }
    }

    #pragma unroll
    for (int i = 0; i < 2; i++)
        #pragma unroll
        for (int j = 0; j < 4; j++) {
            int r = row0 + wm * 32 + i * 16;
            int c = col0 + wn * 64 + j * 16;
            float* Cp = C + (size_t)r * NP + c;
            if (RESID) {
                wmma::fragment<wmma::accumulator, 16, 16, 16, float> rf;
                wmma::load_matrix_sync(rf, R + (size_t)r * NP + c, NP, wmma::mem_row_major);
                #pragma unroll
                for (int e = 0; e < rf.num_elements; e++) acc[i][j].x[e] += rf.x[e];
            }
            wmma::store_matrix_sync(Cp, acc[i][j], NP, wmma::mem_row_major);
        }
}

// ---------------- 3) causal depthwise conv (K=4) + SiLU ----------------------
__global__ void conv_kernel(const float* __restrict__ cw, const float* __restrict__ cb) {
    int id = blockIdx.x * blockDim.x + threadIdx.x;
    if (id >= NBT * CONVCH) return;
    int c  = id % CONVCH;
    int bt = id / CONVCH;
    int t  = bt % LSEQ;
    int b  = bt / LSEQ;
    const float* src = g_zx + (size_t)(b * LSEQ) * DPROJP + DINNER + c;
    float acc = cb[c];
    #pragma unroll
    for (int k = 0; k < 4; k++) {
        int ti = t - 3 + k;
        if (ti >= 0) acc = fmaf(cw[c * 4 + k], src[(size_t)ti * DPROJP], acc);
    }
    g_xbc[id] = acc / (1.f + expf(-acc));   // SiLU
}

// ---------------- 4) dt softplus + dA ----------------------------------------
__global__ void dt_kernel(const float* __restrict__ dt_bias, const float* __restrict__ A_log) {
    int id = blockIdx.x * blockDim.x + threadIdx.x;
    if (id >= NBT * NHEADS) return;
    int h  = id % NHEADS;
    int bt = id / NHEADS;
    float v  = g_zx[(size_t)bt * DPROJP + (DINNER + DINNER + 2 * DSTATE) + h] + dt_bias[h];
    float sp = (v > 20.f) ? v : log1pf(expf(v));
    g_dt[id] = sp;
    g_dA[id] = expf(-expf(A_log[h]) * sp);
}

// ---------------- 5) selective scan: smem-staged chunks + f32x2 --------------
__global__ void __launch_bounds__(512) scan_kernel(const float* __restrict__ Dv) {
    __shared__ float sBC[TCH][256];
    __shared__ float sX [TCH][64];
    __shared__ float sdA[TCH];
    __shared__ float sdt[TCH];

    int blk = blockIdx.x;
    int b = blk / NHEADS, h = blk % NHEADS;
    int tid = threadIdx.x;
    int p = tid >> 3, sub = tid & 7, n0 = sub * 16;

    const float* base = g_xbc + (size_t)(b * LSEQ) * CONVCH;
    const float* dAb  = g_dA + (b * LSEQ) * NHEADS + h;
    const float* dtb  = g_dt + (b * LSEQ) * NHEADS + h;
    float Dh = Dv[h];
    float* yb = g_y + (size_t)(b * LSEQ) * DINNER + h * HEADDIM + p;

    u64 hs[8];
    #pragma unroll
    for (int i = 0; i < 8; i++) hs[i] = 0ull;

    for (int t0 = 0; t0 < LSEQ; t0 += TCH) {
        __syncthreads();
        #pragma unroll
        for (int i = 0; i < 4; i++) {
            int idx = tid + 512 * i;
            int r = idx >> 6, c = (idx & 63) * 4;
            *(float4*)&sBC[r][c] =
                *(const float4*)(base + (size_t)(t0 + r) * CONVCH + DINNER + c);
        }
        {
            int r = tid >> 4, c = (tid & 15) * 4;
            *(float4*)&sX[r][c] =
                *(const float4*)(base + (size_t)(t0 + r) * CONVCH + h * HEADDIM + c);
        }
        if (tid < TCH)            sdA[tid]       = dAb[(t0 + tid) * NHEADS];
        else if (tid < 2 * TCH)   sdt[tid - TCH] = dtb[(t0 + tid - TCH) * NHEADS];
        __syncthreads();

        for (int tt = 0; tt < TCH; tt++) {
            float cdA = sdA[tt], cdt = sdt[tt], cx = sX[tt][p];
            float dtx = cdt * cx;
            u64 cdA2 = pk2(cdA, cdA);
            u64 dtx2 = pk2(dtx, dtx);
            u64 acc2 = 0ull;
            #pragma unroll
            for (int i = 0; i < 4; i++) {
                float4 bv = *(const float4*)&sBC[tt][n0 + i * 4];
                float4 cv = *(const float4*)&sBC[tt][128 + n0 + i * 4];
                u64 b01 = pk2(bv.x, bv.y), b23 = pk2(bv.z, bv.w);
                u64 c01 = pk2(cv.x, cv.y), c23 = pk2(cv.z, cv.w);
                hs[i*2]   = ffma2(cdA2, hs[i*2],   fmul2(dtx2, b01));
                acc2      = ffma2(hs[i*2],   c01, acc2);
                hs[i*2+1] = ffma2(cdA2, hs[i*2+1], fmul2(dtx2, b23));
                acc2      = ffma2(hs[i*2+1], c23, acc2);
            }
            float ax, ay; up2(acc2, ax, ay);
            float acc = ax + ay;
            acc += __shfl_down_sync(0xffffffffu, acc, 4, 8);
            acc += __shfl_down_sync(0xffffffffu, acc, 2, 8);
            acc += __shfl_down_sync(0xffffffffu, acc, 1, 8);
            if (sub == 0) yb[(size_t)(t0 + tt) * DINNER] = acc + Dh * cx;
        }
    }
}

// ---------------- 6) gate (y * silu(z)) + RMSNorm (fp16 output) --------------
__global__ void __launch_bounds__(256) gate_kernel(const float* __restrict__ norm_w) {
    __shared__ float red[32];
    int row = blockIdx.x;
    const float* zr = g_zx + (size_t)row * DPROJP;
    const float* yr = g_y + (size_t)row * DINNER;
    __half* yo = g_yh + (size_t)row * DINNER;
    float g[6], ss = 0.f;
    #pragma unroll
    for (int i = 0; i < 6; i++) {
        int c = threadIdx.x + i * 256;
        float z = zr[c];
        float y = yr[c];
        float gv = y * (z / (1.f + expf(-z)));
        g[i] = gv;
        ss += gv * gv;
    }
    float tot = block_reduce_sum(ss, red);
    float inv = rsqrtf(tot / DINNER + EPSV);
    #pragma unroll
    for (int i = 0; i < 6; i++) {
        int c = threadIdx.x + i * 256;
        yo[c] = __float2half_rn(g[i] * inv * norm_w[c]);
    }
}

// ---------------- launcher ----------------------------------------------------
extern "C" void kernel_launch(void* const* d_in, const int* in_sizes, int n_in,
                              void* d_out, int out_size) {
    const float* x       = (const float*)d_in[0];
    const float* ln_w    = (const float*)d_in[1];
    const float* ln_b    = (const float*)d_in[2];
    const float* W_in    = (const float*)d_in[3];
    const float* conv_w  = (const float*)d_in[4];
    const float* conv_b  = (const float*)d_in[5];
    const float* A_log   = (const float*)d_in[6];
    const float* Dv      = (const float*)d_in[7];
    const float* dt_bias = (const float*)d_in[8];
    const float* norm_w  = (const float*)d_in[9];
    const float* W_out   = (const float*)d_in[10];
    float* out = (float*)d_out;

    __half *puh, *pyh, *pwinh, *pwouth;
    float  *pzx;
    cudaGetSymbolAddress((void**)&puh,    g_uh);
    cudaGetSymbolAddress((void**)&pzx,    g_zx);
    cudaGetSymbolAddress((void**)&pyh,    g_yh);
    cudaGetSymbolAddress((void**)&pwinh,  g_winh);
    cudaGetSymbolAddress((void**)&pwouth, g_wouth);

    cudaFuncSetAttribute(gemm_fp16<false>, cudaFuncAttributeMaxDynamicSharedMemorySize, GEMM_SMEM);
    cudaFuncSetAttribute(gemm_fp16<true>,  cudaFuncAttributeMaxDynamicSharedMemorySize, GEMM_SMEM);

    cvt_win_kernel <<<(DMODEL * DPROJP + 255) / 256, 256>>>(W_in);     // idx 0
    cvt_wout_kernel<<<(DINNER * DMODEL + 255) / 256, 256>>>(W_out);    // idx 1

    ln_kernel<<<NBT, 256>>>(x, ln_w, ln_b);                            // idx 2

    // GEMM1 (app launch idx 3 — the profiled slot): [16384x768]@[768x3456]
    dim3 g1(DPROJP / 128, NBT / 128);   // 27 x 128
    gemm_fp16<false><<<g1, 256, GEMM_SMEM>>>(puh, pwinh, pzx, nullptr,
                                             DPROJP, DPROJP, DMODEL);

    conv_kernel<<<(NBT * CONVCH + 255) / 256, 256>>>(conv_w, conv_b);
    dt_kernel<<<(NBT * NHEADS + 255) / 256, 256>>>(dt_bias, A_log);

    scan_kernel<<<BSZ * NHEADS, 512>>>(Dv);

    gate_kernel<<<NBT, 256>>>(norm_w);

    // GEMM2: [16384x1536] @ [1536x768] + x -> out
    dim3 g2(DMODEL / 128, NBT / 128);   // 6 x 128
    gemm_fp16<true><<<g2, 256, GEMM_SMEM>>>(pyh, pwouth, out, x,
                                            DMODEL, DMODEL, DINNER);
}

// round 11
// speedup vs baseline: 1.3305x; 1.0189x over previous
#include <cuda_runtime.h>
#include <cuda_fp16.h>
#include <math.h>
#include <cstdint>
#include <mma.h>

using namespace nvcuda;

#define BSZ     4
#define LSEQ    4096
#define DMODEL  768
#define DSTATE  128
#define HEADDIM 64
#define DINNER  1536
#define NHEADS  24
#define DPROJ   3352       // logical in-proj width
#define DPROJP  3456       // padded to 27*128
#define CONVCH  1792       // 1536 + 2*128
#define EPSV    1e-5f
#define NBT     (BSZ*LSEQ) // 16384

#define WINSZ   (DMODEL*DPROJP)     // 2,654,208
#define WOUTSZ  (DINNER*DMODEL)     // 1,179,648
#define CVTB    ((WINSZ + WOUTSZ) / 1024)   // 3744 (exact)

// ---------------- scratch (static device globals) ---------------------------
__device__ __half g_uh   [(size_t)NBT * DMODEL];    // LN output, fp16
__device__ float  g_zx   [(size_t)NBT * DPROJP];    // GEMM1 out, fp32
__device__ float  g_xbc  [(size_t)NBT * CONVCH];
__device__ float  g_y    [(size_t)NBT * DINNER];    // scan out, fp32
__device__ __half g_yh   [(size_t)NBT * DINNER];    // gated+normed, fp16
__device__ float  g_dA   [NBT * NHEADS];
__device__ float  g_dt   [NBT * NHEADS];
__device__ __half g_winh [(size_t)WINSZ];           // fp16, padded cols
__device__ __half g_wouth[(size_t)WOUTSZ];          // fp16

// ---------------- helpers ----------------------------------------------------
__device__ __forceinline__ unsigned smem_u32(const void* p) {
    return (unsigned)__cvta_generic_to_shared(p);
}
#define CP16(dst, src)  asm volatile("cp.async.cg.shared.global [%0], [%1], 16;" :: "r"(dst), "l"(src))
#define CP_COMMIT()     asm volatile("cp.async.commit_group;")
#define CP_WAIT(n)      asm volatile("cp.async.wait_group %0;" :: "n"(n))

__device__ __forceinline__ float block_reduce_sum(float v, float* red) {
    #pragma unroll
    for (int o = 16; o; o >>= 1) v += __shfl_down_sync(0xffffffffu, v, o);
    int lane = threadIdx.x & 31, wid = threadIdx.x >> 5;
    if (lane == 0) red[wid] = v;
    __syncthreads();
    int nw = blockDim.x >> 5;
    v = (threadIdx.x < nw) ? red[threadIdx.x] : 0.f;
    if (wid == 0) {
        #pragma unroll
        for (int o = 16; o; o >>= 1) v += __shfl_down_sync(0xffffffffu, v, o);
        if (lane == 0) red[0] = v;
    }
    __syncthreads();
    return red[0];
}

// ---------------- 0+1) LayerNorm (fp16 out) + weight cvt (grid tail) ---------
__global__ void __launch_bounds__(256) lnfused_kernel(const float* __restrict__ x,
                                                      const float* __restrict__ w,
                                                      const float* __restrict__ b,
                                                      const float* __restrict__ Wi,
                                                      const float* __restrict__ Wo) {
    if (blockIdx.x < NBT) {
        __shared__ float red[32];
        int row = blockIdx.x;
        const float* xr = x + (size_t)row * DMODEL;
        float v[3], s = 0.f, ss = 0.f;
        #pragma unroll
        for (int i = 0; i < 3; i++) {
            v[i] = xr[threadIdx.x + i * 256];
            s += v[i]; ss += v[i] * v[i];
        }
        float tot = block_reduce_sum(s, red);
        __syncthreads();
        float tot2 = block_reduce_sum(ss, red);
        float mu  = tot / DMODEL;
        float var = tot2 / DMODEL - mu * mu;
        float inv = rsqrtf(var + EPSV);
        __half* ur = g_uh + (size_t)row * DMODEL;
        #pragma unroll
        for (int i = 0; i < 3; i++) {
            int c = threadIdx.x + i * 256;
            ur[c] = __float2half_rn((v[i] - mu) * inv * w[c] + b[c]);
        }
    } else {
        int e0 = (blockIdx.x - NBT) * 1024 + threadIdx.x * 4;
        #pragma unroll
        for (int j = 0; j < 4; j++) {
            int e = e0 + j;
            if (e < WINSZ) {
                int r = e / DPROJP, c = e - r * DPROJP;
                g_winh[e] = (c < DPROJ)
                          ? __float2half_rn(Wi[(size_t)r * DPROJ + c])
                          : __half(0.f);
            } else {
                int i2 = e - WINSZ;
                g_wouth[i2] = __float2half_rn(Wo[i2]);
            }
        }
    }
}

// ---------------- FP16 wmma GEMM, 3-stage cp.async ring ----------------------
#define GSTG 3
#define ASTRH 40     // 32 + 8 pad (halves)
#define BSTRH 136    // 128 + 8 pad
#define A_ELEMH (128 * ASTRH)
#define B_ELEMH (32 * BSTRH)
#define STG_ELEMH (A_ELEMH + B_ELEMH)
#define GEMM_SMEM (GSTG * STG_ELEMH * 2)   // 56,832 B

template<bool RESID>
__global__ void __launch_bounds__(256, 2)
gemm_fp16(const __half* __restrict__ A, const __half* __restrict__ B,
          float* __restrict__ C, const float* __restrict__ R,
          int NP, int NB, int K) {
    extern __shared__ __half hsm[];
    __half* As = hsm;
    __half* Bs = hsm + GSTG * A_ELEMH;

    int tid  = threadIdx.x;
    int warp = tid >> 5, wm = warp >> 1, wn = warp & 1;
    int row0 = blockIdx.y * 128, col0 = blockIdx.x * 128;

    wmma::fragment<wmma::accumulator, 16, 16, 16, float> acc[2][4];
    #pragma unroll
    for (int i = 0; i < 2; i++)
        #pragma unroll
        for (int j = 0; j < 4; j++) wmma::fill_fragment(acc[i][j], 0.f);

    int a_r = tid >> 2, a_c = (tid & 3) * 8;
    int b_r = tid >> 4, b_c = (tid & 15) * 8;

    auto issue_stage = [&](int s, int k0) {
        __half* Ad = As + s * A_ELEMH;
        __half* Bd = Bs + s * B_ELEMH;
        #pragma unroll
        for (int u = 0; u < 2; u++) {
            int r = a_r + u * 64;
            CP16(smem_u32(Ad + r * ASTRH + a_c),
                 A + (size_t)(row0 + r) * K + k0 + a_c);
        }
        #pragma unroll
        for (int u = 0; u < 2; u++) {
            int r = b_r + u * 16;
            CP16(smem_u32(Bd + r * BSTRH + b_c),
                 B + (size_t)(k0 + r) * NB + col0 + b_c);
        }
    };

    int nk = K / 32;
    issue_stage(0, 0);  CP_COMMIT();
    issue_stage(1, 32); CP_COMMIT();

    for (int i = 0; i < nk; i++) {
        CP_WAIT(1);
        __syncthreads();
        if (i + 2 < nk) issue_stage((i + 2) % GSTG, (i + 2) * 32);
        CP_COMMIT();

        int s = i % GSTG;
        const __half* Ap = As + s * A_ELEMH;
        const __half* Bp = Bs + s * B_ELEMH;
        #pragma unroll
        for (int kk = 0; kk < 32; kk += 16) {
            wmma::fragment<wmma::matrix_a, 16, 16, 16, __half, wmma::row_major> af[2];
            #pragma unroll
            for (int a = 0; a < 2; a++)
                wmma::load_matrix_sync(af[a], Ap + (wm * 32 + a * 16) * ASTRH + kk, ASTRH);
            #pragma unroll
            for (int b2 = 0; b2 < 4; b2++) {
                wmma::fragment<wmma::matrix_b, 16, 16, 16, __half, wmma::row_major> bf;
                wmma::load_matrix_sync(bf, Bp + kk * BSTRH + wn * 64 + b2 * 16, BSTRH);
                wmma::mma_sync(acc[0][b2], af[0], bf, acc[0][b2]);
                wmma::mma_sync(acc[1][b2], af[1], bf, acc[1][b2]);
            }
        }
    }

    #pragma unroll
    for (int i = 0; i < 2; i++)
        #pragma unroll
        for (int j = 0; j < 4; j++) {
            int r = row0 + wm * 32 + i * 16;
            int c = col0 + wn * 64 + j * 16;
            float* Cp = C + (size_t)r * NP + c;
            if (RESID) {
                wmma::fragment<wmma::accumulator, 16, 16, 16, float> rf;
                wmma::load_matrix_sync(rf, R + (size_t)r * NP + c, NP, wmma::mem_row_major);
                #pragma unroll
                for (int e = 0; e < rf.num_elements; e++) acc[i][j].x[e] += rf.x[e];
            }
            wmma::store_matrix_sync(Cp, acc[i][j], NP, wmma::mem_row_major);
        }
}

// ---------------- 2) conv(K=4)+SiLU with dt/dA in grid tail -------------------
#define CONVBLK ((NBT * CONVCH) / 256)          // 114,688 (exact)
#define DTBLK   ((NBT * NHEADS) / 256)          // 1,536   (exact)
__global__ void __launch_bounds__(256) convdt_kernel(const float* __restrict__ cw,
                                                     const float* __restrict__ cb,
                                                     const float* __restrict__ dt_bias,
                                                     const float* __restrict__ A_log) {
    if (blockIdx.x < CONVBLK) {
        int id = blockIdx.x * 256 + threadIdx.x;
        int c  = id % CONVCH;
        int bt = id / CONVCH;
        int t  = bt % LSEQ;
        int b  = bt / LSEQ;
        const float* src = g_zx + (size_t)(b * LSEQ) * DPROJP + DINNER + c;
        float acc = cb[c];
        #pragma unroll
        for (int k = 0; k < 4; k++) {
            int ti = t - 3 + k;
            if (ti >= 0) acc = fmaf(cw[c * 4 + k], src[(size_t)ti * DPROJP], acc);
        }
        g_xbc[id] = acc / (1.f + expf(-acc));   // SiLU
    } else {
        int id = (blockIdx.x - CONVBLK) * 256 + threadIdx.x;
        int h  = id % NHEADS;
        int bt = id / NHEADS;
        float v  = g_zx[(size_t)bt * DPROJP + (DINNER + DINNER + 2 * DSTATE) + h] + dt_bias[h];
        float sp = (v > 20.f) ? v : log1pf(expf(v));
        g_dt[id] = sp;
        g_dA[id] = expf(-expf(A_log[h]) * sp);
    }
}

// ---------------- 3) selective scan (global loads, p-split x2) ----------------
// 192 blocks = (b, h, p-half). 256 threads: p = half*32 + tid/8, sub = tid%8,
// 16 states per thread, 1-step software prefetch (proven R1 structure).
__global__ void __launch_bounds__(256) scan_kernel(const float* __restrict__ Dv) {
    int blk = blockIdx.x;
    int b  = blk / (NHEADS * 2);
    int rm = blk % (NHEADS * 2);
    int h  = rm >> 1, ph = rm & 1;
    int tid = threadIdx.x;
    int p = ph * 32 + (tid >> 3), sub = tid & 7, n0 = sub * 16;

    const float* Bb  = g_xbc + (size_t)(b * LSEQ) * CONVCH + DINNER + n0;
    const float* Cb  = Bb + DSTATE;
    const float* xb  = g_xbc + (size_t)(b * LSEQ) * CONVCH + h * HEADDIM + p;
    const float* dAb = g_dA + (b * LSEQ) * NHEADS + h;
    const float* dtb = g_dt + (b * LSEQ) * NHEADS + h;
    float Dh = Dv[h];
    float* yb = g_y + (size_t)(b * LSEQ) * DINNER + h * HEADDIM + p;

    float hs[16];
    #pragma unroll
    for (int i = 0; i < 16; i++) hs[i] = 0.f;

    float4 nB[4], nC[4];
    float ndA, ndt, nx;
    #pragma unroll
    for (int i = 0; i < 4; i++) {
        nB[i] = *(const float4*)(Bb + i * 4);
        nC[i] = *(const float4*)(Cb + i * 4);
    }
    ndA = dAb[0]; ndt = dtb[0]; nx = xb[0];

    for (int t = 0; t < LSEQ; t++) {
        float4 cB[4], cC[4];
        #pragma unroll
        for (int i = 0; i < 4; i++) { cB[i] = nB[i]; cC[i] = nC[i]; }
        float cdA = ndA, cdt = ndt, cx = nx;
        if (t + 1 < LSEQ) {
            const float* B1 = Bb + (size_t)(t + 1) * CONVCH;
            const float* C1 = Cb + (size_t)(t + 1) * CONVCH;
            #pragma unroll
            for (int i = 0; i < 4; i++) {
                nB[i] = *(const float4*)(B1 + i * 4);
                nC[i] = *(const float4*)(C1 + i * 4);
            }
            ndA = dAb[(t + 1) * NHEADS];
            ndt = dtb[(t + 1) * NHEADS];
            nx  = xb[(size_t)(t + 1) * CONVCH];
        }
        float dtx = cdt * cx;
        float acc = 0.f;
        #pragma unroll
        for (int i = 0; i < 4; i++) {
            float*       hv = hs + i * 4;
            const float* bp = (const float*)&cB[i];
            const float* cp = (const float*)&cC[i];
            #pragma unroll
            for (int j = 0; j < 4; j++) {
                hv[j] = fmaf(cdA, hv[j], dtx * bp[j]);
                acc   = fmaf(hv[j], cp[j], acc);
            }
        }
        acc += __shfl_down_sync(0xffffffffu, acc, 4, 8);
        acc += __shfl_down_sync(0xffffffffu, acc, 2, 8);
        acc += __shfl_down_sync(0xffffffffu, acc, 1, 8);
        if (sub == 0) yb[(size_t)t * DINNER] = acc + Dh * cx;
    }
}

// ---------------- 4) gate (y * silu(z)) + RMSNorm (fp16 output) ---------------
__global__ void __launch_bounds__(256) gate_kernel(const float* __restrict__ norm_w) {
    __shared__ float red[32];
    int row = blockIdx.x;
    const float* zr = g_zx + (size_t)row * DPROJP;
    const float* yr = g_y + (size_t)row * DINNER;
    __half* yo = g_yh + (size_t)row * DINNER;
    float g[6], ss = 0.f;
    #pragma unroll
    for (int i = 0; i < 6; i++) {
        int c = threadIdx.x + i * 256;
        float z = zr[c];
        float y = yr[c];
        float gv = y * (z / (1.f + expf(-z)));
        g[i] = gv;
        ss += gv * gv;
    }
    float tot = block_reduce_sum(ss, red);
    float inv = rsqrtf(tot / DINNER + EPSV);
    #pragma unroll
    for (int i = 0; i < 6; i++) {
        int c = threadIdx.x + i * 256;
        yo[c] = __float2half_rn(g[i] * inv * norm_w[c]);
    }
}

// ---------------- launcher ----------------------------------------------------
extern "C" void kernel_launch(void* const* d_in, const int* in_sizes, int n_in,
                              void* d_out, int out_size) {
    const float* x       = (const float*)d_in[0];
    const float* ln_w    = (const float*)d_in[1];
    const float* ln_b    = (const float*)d_in[2];
    const float* W_in    = (const float*)d_in[3];
    const float* conv_w  = (const float*)d_in[4];
    const float* conv_b  = (const float*)d_in[5];
    const float* A_log   = (const float*)d_in[6];
    const float* Dv      = (const float*)d_in[7];
    const float* dt_bias = (const float*)d_in[8];
    const float* norm_w  = (const float*)d_in[9];
    const float* W_out   = (const float*)d_in[10];
    float* out = (float*)d_out;

    __half *puh, *pyh, *pwinh, *pwouth;
    float  *pzx;
    cudaGetSymbolAddress((void**)&puh,    g_uh);
    cudaGetSymbolAddress((void**)&pzx,    g_zx);
    cudaGetSymbolAddress((void**)&pyh,    g_yh);
    cudaGetSymbolAddress((void**)&pwinh,  g_winh);
    cudaGetSymbolAddress((void**)&pwouth, g_wouth);

    cudaFuncSetAttribute(gemm_fp16<false>, cudaFuncAttributeMaxDynamicSharedMemorySize, GEMM_SMEM);
    cudaFuncSetAttribute(gemm_fp16<true>,  cudaFuncAttributeMaxDynamicSharedMemorySize, GEMM_SMEM);

    // idx 0: LN + weight conversion (grid tail)
    lnfused_kernel<<<NBT + CVTB, 256>>>(x, ln_w, ln_b, W_in, W_out);

    // idx 1: GEMM1 [16384x768]@[768x3456]
    dim3 g1(DPROJP / 128, NBT / 128);   // 27 x 128
    gemm_fp16<false><<<g1, 256, GEMM_SMEM>>>(puh, pwinh, pzx, nullptr,
                                             DPROJP, DPROJP, DMODEL);

    // idx 2: conv + SiLU, dt/dA in tail
    convdt_kernel<<<CONVBLK + DTBLK, 256>>>(conv_w, conv_b, dt_bias, A_log);

    // idx 3: scan  <-- profiled slot
    scan_kernel<<<BSZ * NHEADS * 2, 256>>>(Dv);

    // idx 4: gate + RMSNorm
    gate_kernel<<<NBT, 256>>>(norm_w);

    // idx 5: GEMM2 [16384x1536]@[1536x768] + x
    dim3 g2(DMODEL / 128, NBT / 128);   // 6 x 128
    gemm_fp16<true><<<g2, 256, GEMM_SMEM>>>(pyh, pwouth, out, x,
                                            DMODEL, DMODEL, DINNER);
}

// round 12
// speedup vs baseline: 3.0724x; 2.3092x over previous
#include <cuda_runtime.h>
#include <cuda_fp16.h>
#include <math.h>
#include <cstdint>
#include <mma.h>

using namespace nvcuda;

#define BSZ     4
#define LSEQ    4096
#define DMODEL  768
#define DSTATE  128
#define HEADDIM 64
#define DINNER  1536
#define NHEADS  24
#define DPROJ   3352       // logical in-proj width
#define DPROJP  3456       // padded to 27*128
#define CONVCH  1792       // 1536 + 2*128
#define EPSV    1e-5f
#define NBT     (BSZ*LSEQ) // 16384

#define QCH     128                 // scan chunk length
#define NCH     (LSEQ/QCH)          // 32 chunks
#define NBH     (BSZ*NHEADS)        // 96
#define STATE_SZ (HEADDIM*DSTATE)   // 8192 per (b,h)

#define WINSZ   (DMODEL*DPROJP)     // 2,654,208
#define WOUTSZ  (DINNER*DMODEL)     // 1,179,648
#define CVTB    ((WINSZ + WOUTSZ) / 1024)   // 3744 (exact)

typedef unsigned long long u64;

// ---------------- scratch (static device globals) ---------------------------
__device__ __half g_uh   [(size_t)NBT * DMODEL];    // LN output, fp16
__device__ float  g_zx   [(size_t)NBT * DPROJP];    // GEMM1 out, fp32
__device__ float  g_xbc  [(size_t)NBT * CONVCH];
__device__ float  g_y    [(size_t)NBT * DINNER];    // scan out, fp32
__device__ __half g_yh   [(size_t)NBT * DINNER];    // gated+normed, fp16
__device__ float  g_dA   [NBT * NHEADS];
__device__ float  g_dt   [NBT * NHEADS];
__device__ __half g_winh [(size_t)WINSZ];           // fp16, padded cols
__device__ __half g_wouth[(size_t)WOUTSZ];          // fp16
// chunked-scan scratch: layout [bh*NCH + c][n(128)][p(64)]
__device__ float  g_U    [(size_t)NBH * NCH * STATE_SZ];   // chunk local sums
__device__ float  g_hc   [(size_t)NBH * NCH * STATE_SZ];   // chunk start states
__device__ float  g_P    [NBH * NCH];                      // chunk decay products

// ---------------- helpers ----------------------------------------------------
__device__ __forceinline__ u64 pk2(float lo, float hi) {
    u64 d; asm("mov.b64 %0, {%1, %2};" : "=l"(d) : "f"(lo), "f"(hi)); return d;
}
__device__ __forceinline__ void up2(u64 v, float& lo, float& hi) {
    asm("mov.b64 {%0, %1}, %2;" : "=f"(lo), "=f"(hi) : "l"(v));
}
__device__ __forceinline__ u64 ffma2(u64 a, u64 b, u64 c) {
    u64 d; asm("fma.rn.f32x2 %0, %1, %2, %3;" : "=l"(d) : "l"(a), "l"(b), "l"(c)); return d;
}
__device__ __forceinline__ u64 fmul2(u64 a, u64 b) {
    u64 d; asm("mul.rn.f32x2 %0, %1, %2;" : "=l"(d) : "l"(a), "l"(b)); return d;
}
__device__ __forceinline__ unsigned smem_u32(const void* p) {
    return (unsigned)__cvta_generic_to_shared(p);
}
#define CP16(dst, src)  asm volatile("cp.async.cg.shared.global [%0], [%1], 16;" :: "r"(dst), "l"(src))
#define CP_COMMIT()     asm volatile("cp.async.commit_group;")
#define CP_WAIT(n)      asm volatile("cp.async.wait_group %0;" :: "n"(n))

__device__ __forceinline__ float block_reduce_sum(float v, float* red) {
    #pragma unroll
    for (int o = 16; o; o >>= 1) v += __shfl_down_sync(0xffffffffu, v, o);
    int lane = threadIdx.x & 31, wid = threadIdx.x >> 5;
    if (lane == 0) red[wid] = v;
    __syncthreads();
    int nw = blockDim.x >> 5;
    v = (threadIdx.x < nw) ? red[threadIdx.x] : 0.f;
    if (wid == 0) {
        #pragma unroll
        for (int o = 16; o; o >>= 1) v += __shfl_down_sync(0xffffffffu, v, o);
        if (lane == 0) red[0] = v;
    }
    __syncthreads();
    return red[0];
}

// ---------------- 0+1) LayerNorm (fp16 out) + weight cvt (grid tail) ---------
__global__ void __launch_bounds__(256) lnfused_kernel(const float* __restrict__ x,
                                                      const float* __restrict__ w,
                                                      const float* __restrict__ b,
                                                      const float* __restrict__ Wi,
                                                      const float* __restrict__ Wo) {
    if (blockIdx.x < NBT) {
        __shared__ float red[32];
        int row = blockIdx.x;
        const float* xr = x + (size_t)row * DMODEL;
        float v[3], s = 0.f, ss = 0.f;
        #pragma unroll
        for (int i = 0; i < 3; i++) {
            v[i] = xr[threadIdx.x + i * 256];
            s += v[i]; ss += v[i] * v[i];
        }
        float tot = block_reduce_sum(s, red);
        __syncthreads();
        float tot2 = block_reduce_sum(ss, red);
        float mu  = tot / DMODEL;
        float var = tot2 / DMODEL - mu * mu;
        float inv = rsqrtf(var + EPSV);
        __half* ur = g_uh + (size_t)row * DMODEL;
        #pragma unroll
        for (int i = 0; i < 3; i++) {
            int c = threadIdx.x + i * 256;
            ur[c] = __float2half_rn((v[i] - mu) * inv * w[c] + b[c]);
        }
    } else {
        int e0 = (blockIdx.x - NBT) * 1024 + threadIdx.x * 4;
        #pragma unroll
        for (int j = 0; j < 4; j++) {
            int e = e0 + j;
            if (e < WINSZ) {
                int r = e / DPROJP, c = e - r * DPROJP;
                g_winh[e] = (c < DPROJ)
                          ? __float2half_rn(Wi[(size_t)r * DPROJ + c])
                          : __half(0.f);
            } else {
                int i2 = e - WINSZ;
                g_wouth[i2] = __float2half_rn(Wo[i2]);
            }
        }
    }
}

// ---------------- FP16 wmma GEMM, 3-stage cp.async ring ----------------------
#define GSTG 3
#define ASTRH 40
#define BSTRH 136
#define A_ELEMH (128 * ASTRH)
#define B_ELEMH (32 * BSTRH)
#define STG_ELEMH (A_ELEMH + B_ELEMH)
#define GEMM_SMEM (GSTG * STG_ELEMH * 2)   // 56,832 B

template<bool RESID>
__global__ void __launch_bounds__(256, 2)
gemm_fp16(const __half* __restrict__ A, const __half* __restrict__ B,
          float* __restrict__ C, const float* __restrict__ R,
          int NP, int NB, int K) {
    extern __shared__ __half hsm[];
    __half* As = hsm;
    __half* Bs = hsm + GSTG * A_ELEMH;

    int tid  = threadIdx.x;
    int warp = tid >> 5, wm = warp >> 1, wn = warp & 1;
    int row0 = blockIdx.y * 128, col0 = blockIdx.x * 128;

    wmma::fragment<wmma::accumulator, 16, 16, 16, float> acc[2][4];
    #pragma unroll
    for (int i = 0; i < 2; i++)
        #pragma unroll
        for (int j = 0; j < 4; j++) wmma::fill_fragment(acc[i][j], 0.f);

    int a_r = tid >> 2, a_c = (tid & 3) * 8;
    int b_r = tid >> 4, b_c = (tid & 15) * 8;

    auto issue_stage = [&](int s, int k0) {
        __half* Ad = As + s * A_ELEMH;
        __half* Bd = Bs + s * B_ELEMH;
        #pragma unroll
        for (int u = 0; u < 2; u++) {
            int r = a_r + u * 64;
            CP16(smem_u32(Ad + r * ASTRH + a_c),
                 A + (size_t)(row0 + r) * K + k0 + a_c);
        }
        #pragma unroll
        for (int u = 0; u < 2; u++) {
            int r = b_r + u * 16;
            CP16(smem_u32(Bd + r * BSTRH + b_c),
                 B + (size_t)(k0 + r) * NB + col0 + b_c);
        }
    };

    int nk = K / 32;
    issue_stage(0, 0);  CP_COMMIT();
    issue_stage(1, 32); CP_COMMIT();

    for (int i = 0; i < nk; i++) {
        CP_WAIT(1);
        __syncthreads();
        if (i + 2 < nk) issue_stage((i + 2) % GSTG, (i + 2) * 32);
        CP_COMMIT();

        int s = i % GSTG;
        const __half* Ap = As + s * A_ELEMH;
        const __half* Bp = Bs + s * B_ELEMH;
        #pragma unroll
        for (int kk = 0; kk < 32; kk += 16) {
            wmma::fragment<wmma::matrix_a, 16, 16, 16, __half, wmma::row_major> af[2];
            #pragma unroll
            for (int a = 0; a < 2; a++)
                wmma::load_matrix_sync(af[a], Ap + (wm * 32 + a * 16) * ASTRH + kk, ASTRH);
            #pragma unroll
            for (int b2 = 0; b2 < 4; b2++) {
                wmma::fragment<wmma::matrix_b, 16, 16, 16, __half, wmma::row_major> bf;
                wmma::load_matrix_sync(bf, Bp + kk * BSTRH + wn * 64 + b2 * 16, BSTRH);
                wmma::mma_sync(acc[0][b2], af[0], bf, acc[0][b2]);
                wmma::mma_sync(acc[1][b2], af[1], bf, acc[1][b2]);
            }
        }
    }

    #pragma unroll
    for (int i = 0; i < 2; i++)
        #pragma unroll
        for (int j = 0; j < 4; j++) {
            int r = row0 + wm * 32 + i * 16;
            int c = col0 + wn * 64 + j * 16;
            float* Cp = C + (size_t)r * NP + c;
            if (RESID) {
                wmma::fragment<wmma::accumulator, 16, 16, 16, float> rf;
                wmma::load_matrix_sync(rf, R + (size_t)r * NP + c, NP, wmma::mem_row_major);
                #pragma unroll
                for (int e = 0; e < rf.num_elements; e++) acc[i][j].x[e] += rf.x[e];
            }
            wmma::store_matrix_sync(Cp, acc[i][j], NP, wmma::mem_row_major);
        }
}

// ---------------- 2) conv(K=4)+SiLU with dt/dA in grid tail -------------------
#define CONVBLK ((NBT * CONVCH) / 256)
#define DTBLK   ((NBT * NHEADS) / 256)
__global__ void __launch_bounds__(256) convdt_kernel(const float* __restrict__ cw,
                                                     const float* __restrict__ cb,
                                                     const float* __restrict__ dt_bias,
                                                     const float* __restrict__ A_log) {
    if (blockIdx.x < CONVBLK) {
        int id = blockIdx.x * 256 + threadIdx.x;
        int c  = id % CONVCH;
        int bt = id / CONVCH;
        int t  = bt % LSEQ;
        int b  = bt / LSEQ;
        const float* src = g_zx + (size_t)(b * LSEQ) * DPROJP + DINNER + c;
        float acc = cb[c];
        #pragma unroll
        for (int k = 0; k < 4; k++) {
            int ti = t - 3 + k;
            if (ti >= 0) acc = fmaf(cw[c * 4 + k], src[(size_t)ti * DPROJP], acc);
        }
        g_xbc[id] = acc / (1.f + expf(-acc));   // SiLU
    } else {
        int id = (blockIdx.x - CONVBLK) * 256 + threadIdx.x;
        int h  = id % NHEADS;
        int bt = id / NHEADS;
        float v  = g_zx[(size_t)bt * DPROJP + (DINNER + DINNER + 2 * DSTATE) + h] + dt_bias[h];
        float sp = (v > 20.f) ? v : log1pf(expf(v));
        g_dt[id] = sp;
        g_dA[id] = expf(-expf(A_log[h]) * sp);
    }
}

// ---------------- 3a) scan pass A: per-chunk local state U + decay P ---------
// grid = NBH*NCH (3072). 256 threads: warp = (ph = wid&1, g = wid>>1);
// p = ph*32 + lane (lane = p → warp-uniform B loads), states n0 = g*32 .. +32.
__global__ void __launch_bounds__(256) scanA_kernel() {
    int blk = blockIdx.x;
    int c  = blk & (NCH - 1);
    int bh = blk >> 5;
    int b = bh / NHEADS, h = bh % NHEADS;
    int tid = threadIdx.x;
    int wid = tid >> 5, lane = tid & 31;
    int ph = wid & 1, g = wid >> 1;
    int p = ph * 32 + lane, n0 = g * 32;
    int t0 = c * QCH;

    const float* base = g_xbc + (size_t)(b * LSEQ + t0) * CONVCH;
    const float* dAb  = g_dA + (b * LSEQ + t0) * NHEADS + h;
    const float* dtb  = g_dt + (b * LSEQ + t0) * NHEADS + h;

    u64 hs[16];
    #pragma unroll
    for (int i = 0; i < 16; i++) hs[i] = 0ull;
    float Pacc = 1.f;

    for (int tt = 0; tt < QCH; tt++) {
        const float* row = base + (size_t)tt * CONVCH;
        float cdA = dAb[tt * NHEADS];
        float cdt = dtb[tt * NHEADS];
        float cx  = row[h * HEADDIM + p];
        float dtx = cdt * cx;
        u64 cdA2 = pk2(cdA, cdA), dtx2 = pk2(dtx, dtx);
        const float4* Bp = (const float4*)(row + DINNER + n0);
        #pragma unroll
        for (int j = 0; j < 8; j++) {
            float4 bv = Bp[j];                       // warp-uniform broadcast
            u64 b01 = pk2(bv.x, bv.y), b23 = pk2(bv.z, bv.w);
            hs[2*j]   = ffma2(cdA2, hs[2*j],   fmul2(dtx2, b01));
            hs[2*j+1] = ffma2(cdA2, hs[2*j+1], fmul2(dtx2, b23));
        }
        Pacc *= cdA;
    }

    float* Up = g_U + (size_t)blk * STATE_SZ;        // [n][p] layout
    #pragma unroll
    for (int j = 0; j < 16; j++) {
        float lo, hi; up2(hs[j], lo, hi);
        int n = n0 + j * 2;
        Up[(size_t)n * HEADDIM + p]       = lo;      // lanes → consecutive p: coalesced
        Up[(size_t)(n + 1) * HEADDIM + p] = hi;
    }
    if (tid == 0) g_P[blk] = Pacc;
}

// ---------------- 3b) scan pass B: sequential chunk-state chain --------------
// grid = NBH*8 (768); each block owns 1024 of the 8192 state elements.
__global__ void __launch_bounds__(256) scanB_kernel() {
    int bh = blockIdx.x >> 3, part = blockIdx.x & 7;
    int e0 = part * 1024 + threadIdx.x;
    float hcur[4] = {0.f, 0.f, 0.f, 0.f};
    for (int c = 0; c < NCH; c++) {
        size_t off = (size_t)(bh * NCH + c) * STATE_SZ + e0;
        float P = g_P[bh * NCH + c];
        #pragma unroll
        for (int k = 0; k < 4; k++) {
            g_hc[off + k * 256] = hcur[k];
            hcur[k] = fmaf(P, hcur[k], g_U[off + k * 256]);
        }
    }
}

// ---------------- 3c) scan pass C: replay chunk from true start, emit y ------
__global__ void __launch_bounds__(256) scanC_kernel(const float* __restrict__ Dv) {
    __shared__ float sY[2][4][64];

    int blk = blockIdx.x;
    int c  = blk & (NCH - 1);
    int bh = blk >> 5;
    int b = bh / NHEADS, h = bh % NHEADS;
    int tid = threadIdx.x;
    int wid = tid >> 5, lane = tid & 31;
    int ph = wid & 1, g = wid >> 1;
    int p = ph * 32 + lane, n0 = g * 32;
    int t0 = c * QCH;

    const float* base = g_xbc + (size_t)(b * LSEQ + t0) * CONVCH;
    const float* dAb  = g_dA + (b * LSEQ + t0) * NHEADS + h;
    const float* dtb  = g_dt + (b * LSEQ + t0) * NHEADS + h;
    float Dh = Dv[h];
    float* ybase = g_y + (size_t)(b * LSEQ + t0) * DINNER + h * HEADDIM;

    // load chunk start state ([n][p] layout, coalesced)
    const float* Hp = g_hc + (size_t)blk * STATE_SZ;
    u64 hs[16];
    #pragma unroll
    for (int j = 0; j < 16; j++) {
        int n = n0 + j * 2;
        float lo = Hp[(size_t)n * HEADDIM + p];
        float hi = Hp[(size_t)(n + 1) * HEADDIM + p];
        hs[j] = pk2(lo, hi);
    }

    int buf = 0;
    for (int tt = 0; tt < QCH; tt++) {
        const float* row = base + (size_t)tt * CONVCH;
        float cdA = dAb[tt * NHEADS];
        float cdt = dtb[tt * NHEADS];
        float cx  = row[h * HEADDIM + p];
        float dtx = cdt * cx;
        u64 cdA2 = pk2(cdA, cdA), dtx2 = pk2(dtx, dtx);
        const float4* Bp = (const float4*)(row + DINNER + n0);
        const float4* Cp = (const float4*)(row + DINNER + DSTATE + n0);
        u64 acc2 = 0ull;
        #pragma unroll
        for (int j = 0; j < 8; j++) {
            float4 bv = Bp[j];                       // uniform broadcast
            float4 cv = Cp[j];
            u64 b01 = pk2(bv.x, bv.y), b23 = pk2(bv.z, bv.w);
            u64 c01 = pk2(cv.x, cv.y), c23 = pk2(cv.z, cv.w);
            hs[2*j]   = ffma2(cdA2, hs[2*j],   fmul2(dtx2, b01));
            acc2      = ffma2(hs[2*j],   c01, acc2);
            hs[2*j+1] = ffma2(cdA2, hs[2*j+1], fmul2(dtx2, b23));
            acc2      = ffma2(hs[2*j+1], c23, acc2);
        }
        float ax, ay; up2(acc2, ax, ay);
        sY[buf][g][p] = ax + ay;
        __syncthreads();
        if (wid < 2) {
            float ys = sY[buf][0][p] + sY[buf][1][p]
                     + sY[buf][2][p] + sY[buf][3][p];
            ybase[(size_t)tt * DINNER + p] = fmaf(Dh, cx, ys);
        }
        buf ^= 1;
    }
}

// ---------------- 4) gate (y * silu(z)) + RMSNorm (fp16 output) ---------------
__global__ void __launch_bounds__(256) gate_kernel(const float* __restrict__ norm_w) {
    __shared__ float red[32];
    int row = blockIdx.x;
    const float* zr = g_zx + (size_t)row * DPROJP;
    const float* yr = g_y + (size_t)row * DINNER;
    __half* yo = g_yh + (size_t)row * DINNER;
    float gbuf[6], ss = 0.f;
    #pragma unroll
    for (int i = 0; i < 6; i++) {
        int c = threadIdx.x + i * 256;
        float z = zr[c];
        float y = yr[c];
        float gv = y * (z / (1.f + expf(-z)));
        gbuf[i] = gv;
        ss += gv * gv;
    }
    float tot = block_reduce_sum(ss, red);
    float inv = rsqrtf(tot / DINNER + EPSV);
    #pragma unroll
    for (int i = 0; i < 6; i++) {
        int c = threadIdx.x + i * 256;
        yo[c] = __float2half_rn(gbuf[i] * inv * norm_w[c]);
    }
}

// ---------------- launcher ----------------------------------------------------
extern "C" void kernel_launch(void* const* d_in, const int* in_sizes, int n_in,
                              void* d_out, int out_size) {
    const float* x       = (const float*)d_in[0];
    const float* ln_w    = (const float*)d_in[1];
    const float* ln_b    = (const float*)d_in[2];
    const float* W_in    = (const float*)d_in[3];
    const float* conv_w  = (const float*)d_in[4];
    const float* conv_b  = (const float*)d_in[5];
    const float* A_log   = (const float*)d_in[6];
    const float* Dv      = (const float*)d_in[7];
    const float* dt_bias = (const float*)d_in[8];
    const float* norm_w  = (const float*)d_in[9];
    const float* W_out   = (const float*)d_in[10];
    float* out = (float*)d_out;

    __half *puh, *pyh, *pwinh, *pwouth;
    float  *pzx;
    cudaGetSymbolAddress((void**)&puh,    g_uh);
    cudaGetSymbolAddress((void**)&pzx,    g_zx);
    cudaGetSymbolAddress((void**)&pyh,    g_yh);
    cudaGetSymbolAddress((void**)&pwinh,  g_winh);
    cudaGetSymbolAddress((void**)&pwouth, g_wouth);

    cudaFuncSetAttribute(gemm_fp16<false>, cudaFuncAttributeMaxDynamicSharedMemorySize, GEMM_SMEM);
    cudaFuncSetAttribute(gemm_fp16<true>,  cudaFuncAttributeMaxDynamicSharedMemorySize, GEMM_SMEM);

    // idx 0: LN + weight conversion (grid tail)
    lnfused_kernel<<<NBT + CVTB, 256>>>(x, ln_w, ln_b, W_in, W_out);

    // idx 1: GEMM1 [16384x768]@[768x3456]
    dim3 g1(DPROJP / 128, NBT / 128);
    gemm_fp16<false><<<g1, 256, GEMM_SMEM>>>(puh, pwinh, pzx, nullptr,
                                             DPROJP, DPROJP, DMODEL);

    // idx 2: conv + SiLU, dt/dA in tail
    convdt_kernel<<<CONVBLK + DTBLK, 256>>>(conv_w, conv_b, dt_bias, A_log);

    // idx 3: scan pass A (profiled slot)
    scanA_kernel<<<NBH * NCH, 256>>>();

    // idx 4: scan pass B (chunk-state chain)
    scanB_kernel<<<NBH * 8, 256>>>();

    // idx 5: scan pass C (emit y)
    scanC_kernel<<<NBH * NCH, 256>>>(Dv);

    // idx 6: gate + RMSNorm
    gate_kernel<<<NBT, 256>>>(norm_w);

    // idx 7: GEMM2 [16384x1536]@[1536x768] + x
    dim3 g2(DMODEL / 128, NBT / 128);
    gemm_fp16<true><<<g2, 256, GEMM_SMEM>>>(pyh, pwouth, out, x,
                                            DMODEL, DMODEL, DINNER);
}

// round 13
// speedup vs baseline: 3.7002x; 1.2043x over previous
#include <cuda_runtime.h>
#include <cuda_fp16.h>
#include <math.h>
#include <cstdint>
#include <mma.h>

using namespace nvcuda;

#define BSZ     4
#define LSEQ    4096
#define DMODEL  768
#define DSTATE  128
#define HEADDIM 64
#define DINNER  1536
#define NHEADS  24
#define DPROJ   3352       // logical in-proj width
#define DPROJP  3456       // padded to 27*128
#define CONVCH  1792       // 1536 + 2*128
#define EPSV    1e-5f
#define NBT     (BSZ*LSEQ) // 16384

#define QCH     128                 // scan chunk length
#define NCH     (LSEQ/QCH)          // 32 chunks
#define NBH     (BSZ*NHEADS)        // 96
#define STATE_SZ (HEADDIM*DSTATE)   // 8192 per (b,h)

#define WINSZ   (DMODEL*DPROJP)     // 2,654,208
#define WOUTSZ  (DINNER*DMODEL)     // 1,179,648
#define CVTB    ((WINSZ + WOUTSZ) / 1024)   // 3744 (exact)

typedef unsigned long long u64;

// ---------------- scratch (static device globals) ---------------------------
__device__ __half g_uh   [(size_t)NBT * DMODEL];    // LN output, fp16
__device__ float  g_zx   [(size_t)NBT * DPROJP];    // GEMM1 out, fp32
__device__ float  g_xbc  [(size_t)NBT * CONVCH];
__device__ float  g_y    [(size_t)NBT * DINNER];    // scan out, fp32
__device__ __half g_yh   [(size_t)NBT * DINNER];    // gated+normed, fp16
__device__ float  g_dA   [NBT * NHEADS];
__device__ float  g_dt   [NBT * NHEADS];
__device__ __half g_winh [(size_t)WINSZ];           // fp16, padded cols
__device__ __half g_wouth[(size_t)WOUTSZ];          // fp16
// chunked-scan scratch: layout [bh*NCH + c][n(128)][p(64)]
__device__ float  g_U    [(size_t)NBH * NCH * STATE_SZ];   // chunk local sums
__device__ float  g_hc   [(size_t)NBH * NCH * STATE_SZ];   // chunk start states
__device__ float  g_P    [NBH * NCH];                      // chunk decay products

// ---------------- helpers ----------------------------------------------------
__device__ __forceinline__ u64 pk2(float lo, float hi) {
    u64 d; asm("mov.b64 %0, {%1, %2};" : "=l"(d) : "f"(lo), "f"(hi)); return d;
}
__device__ __forceinline__ void up2(u64 v, float& lo, float& hi) {
    asm("mov.b64 {%0, %1}, %2;" : "=f"(lo), "=f"(hi) : "l"(v));
}
__device__ __forceinline__ u64 ffma2(u64 a, u64 b, u64 c) {
    u64 d; asm("fma.rn.f32x2 %0, %1, %2, %3;" : "=l"(d) : "l"(a), "l"(b), "l"(c)); return d;
}
__device__ __forceinline__ u64 fmul2(u64 a, u64 b) {
    u64 d; asm("mul.rn.f32x2 %0, %1, %2;" : "=l"(d) : "l"(a), "l"(b)); return d;
}
__device__ __forceinline__ unsigned smem_u32(const void* p) {
    return (unsigned)__cvta_generic_to_shared(p);
}
#define CP16(dst, src)  asm volatile("cp.async.cg.shared.global [%0], [%1], 16;" :: "r"(dst), "l"(src))
#define CP_COMMIT()     asm volatile("cp.async.commit_group;")
#define CP_WAIT(n)      asm volatile("cp.async.wait_group %0;" :: "n"(n))

__device__ __forceinline__ float block_reduce_sum(float v, float* red) {
    #pragma unroll
    for (int o = 16; o; o >>= 1) v += __shfl_down_sync(0xffffffffu, v, o);
    int lane = threadIdx.x & 31, wid = threadIdx.x >> 5;
    if (lane == 0) red[wid] = v;
    __syncthreads();
    int nw = blockDim.x >> 5;
    v = (threadIdx.x < nw) ? red[threadIdx.x] : 0.f;
    if (wid == 0) {
        #pragma unroll
        for (int o = 16; o; o >>= 1) v += __shfl_down_sync(0xffffffffu, v, o);
        if (lane == 0) red[0] = v;
    }
    __syncthreads();
    return red[0];
}

// ---------------- 0+1) LayerNorm (fp16 out) + weight cvt (grid tail) ---------
__global__ void __launch_bounds__(256) lnfused_kernel(const float* __restrict__ x,
                                                      const float* __restrict__ w,
                                                      const float* __restrict__ b,
                                                      const float* __restrict__ Wi,
                                                      const float* __restrict__ Wo) {
    if (blockIdx.x < NBT) {
        __shared__ float red[32];
        int row = blockIdx.x;
        const float* xr = x + (size_t)row * DMODEL;
        float v[3], s = 0.f, ss = 0.f;
        #pragma unroll
        for (int i = 0; i < 3; i++) {
            v[i] = xr[threadIdx.x + i * 256];
            s += v[i]; ss += v[i] * v[i];
        }
        float tot = block_reduce_sum(s, red);
        __syncthreads();
        float tot2 = block_reduce_sum(ss, red);
        float mu  = tot / DMODEL;
        float var = tot2 / DMODEL - mu * mu;
        float inv = rsqrtf(var + EPSV);
        __half* ur = g_uh + (size_t)row * DMODEL;
        #pragma unroll
        for (int i = 0; i < 3; i++) {
            int c = threadIdx.x + i * 256;
            ur[c] = __float2half_rn((v[i] - mu) * inv * w[c] + b[c]);
        }
    } else {
        int e0 = (blockIdx.x - NBT) * 1024 + threadIdx.x * 4;
        #pragma unroll
        for (int j = 0; j < 4; j++) {
            int e = e0 + j;
            if (e < WINSZ) {
                int r = e / DPROJP, c = e - r * DPROJP;
                g_winh[e] = (c < DPROJ)
                          ? __float2half_rn(Wi[(size_t)r * DPROJ + c])
                          : __half(0.f);
            } else {
                int i2 = e - WINSZ;
                g_wouth[i2] = __float2half_rn(Wo[i2]);
            }
        }
    }
}

// ---------------- FP16 wmma GEMM, 3-stage cp.async ring ----------------------
#define GSTG 3
#define ASTRH 40
#define BSTRH 136
#define A_ELEMH (128 * ASTRH)
#define B_ELEMH (32 * BSTRH)
#define STG_ELEMH (A_ELEMH + B_ELEMH)
#define GEMM_SMEM (GSTG * STG_ELEMH * 2)   // 56,832 B

template<bool RESID>
__global__ void __launch_bounds__(256, 2)
gemm_fp16(const __half* __restrict__ A, const __half* __restrict__ B,
          float* __restrict__ C, const float* __restrict__ R,
          int NP, int NB, int K) {
    extern __shared__ __half hsm[];
    __half* As = hsm;
    __half* Bs = hsm + GSTG * A_ELEMH;

    int tid  = threadIdx.x;
    int warp = tid >> 5, wm = warp >> 1, wn = warp & 1;
    int row0 = blockIdx.y * 128, col0 = blockIdx.x * 128;

    wmma::fragment<wmma::accumulator, 16, 16, 16, float> acc[2][4];
    #pragma unroll
    for (int i = 0; i < 2; i++)
        #pragma unroll
        for (int j = 0; j < 4; j++) wmma::fill_fragment(acc[i][j], 0.f);

    int a_r = tid >> 2, a_c = (tid & 3) * 8;
    int b_r = tid >> 4, b_c = (tid & 15) * 8;

    auto issue_stage = [&](int s, int k0) {
        __half* Ad = As + s * A_ELEMH;
        __half* Bd = Bs + s * B_ELEMH;
        #pragma unroll
        for (int u = 0; u < 2; u++) {
            int r = a_r + u * 64;
            CP16(smem_u32(Ad + r * ASTRH + a_c),
                 A + (size_t)(row0 + r) * K + k0 + a_c);
        }
        #pragma unroll
        for (int u = 0; u < 2; u++) {
            int r = b_r + u * 16;
            CP16(smem_u32(Bd + r * BSTRH + b_c),
                 B + (size_t)(k0 + r) * NB + col0 + b_c);
        }
    };

    int nk = K / 32;
    issue_stage(0, 0);  CP_COMMIT();
    issue_stage(1, 32); CP_COMMIT();

    for (int i = 0; i < nk; i++) {
        CP_WAIT(1);
        __syncthreads();
        if (i + 2 < nk) issue_stage((i + 2) % GSTG, (i + 2) * 32);
        CP_COMMIT();

        int s = i % GSTG;
        const __half* Ap = As + s * A_ELEMH;
        const __half* Bp = Bs + s * B_ELEMH;
        #pragma unroll
        for (int kk = 0; kk < 32; kk += 16) {
            wmma::fragment<wmma::matrix_a, 16, 16, 16, __half, wmma::row_major> af[2];
            #pragma unroll
            for (int a = 0; a < 2; a++)
                wmma::load_matrix_sync(af[a], Ap + (wm * 32 + a * 16) * ASTRH + kk, ASTRH);
            #pragma unroll
            for (int b2 = 0; b2 < 4; b2++) {
                wmma::fragment<wmma::matrix_b, 16, 16, 16, __half, wmma::row_major> bf;
                wmma::load_matrix_sync(bf, Bp + kk * BSTRH + wn * 64 + b2 * 16, BSTRH);
                wmma::mma_sync(acc[0][b2], af[0], bf, acc[0][b2]);
                wmma::mma_sync(acc[1][b2], af[1], bf, acc[1][b2]);
            }
        }
    }

    #pragma unroll
    for (int i = 0; i < 2; i++)
        #pragma unroll
        for (int j = 0; j < 4; j++) {
            int r = row0 + wm * 32 + i * 16;
            int c = col0 + wn * 64 + j * 16;
            float* Cp = C + (size_t)r * NP + c;
            if (RESID) {
                wmma::fragment<wmma::accumulator, 16, 16, 16, float> rf;
                wmma::load_matrix_sync(rf, R + (size_t)r * NP + c, NP, wmma::mem_row_major);
                #pragma unroll
                for (int e = 0; e < rf.num_elements; e++) acc[i][j].x[e] += rf.x[e];
            }
            wmma::store_matrix_sync(Cp, acc[i][j], NP, wmma::mem_row_major);
        }
}

// ---------------- 2) conv(K=4)+SiLU with dt/dA in grid tail -------------------
#define CONVBLK ((NBT * CONVCH) / 256)
#define DTBLK   ((NBT * NHEADS) / 256)
__global__ void __launch_bounds__(256) convdt_kernel(const float* __restrict__ cw,
                                                     const float* __restrict__ cb,
                                                     const float* __restrict__ dt_bias,
                                                     const float* __restrict__ A_log) {
    if (blockIdx.x < CONVBLK) {
        int id = blockIdx.x * 256 + threadIdx.x;
        int c  = id % CONVCH;
        int bt = id / CONVCH;
        int t  = bt % LSEQ;
        int b  = bt / LSEQ;
        const float* src = g_zx + (size_t)(b * LSEQ) * DPROJP + DINNER + c;
        float acc = cb[c];
        #pragma unroll
        for (int k = 0; k < 4; k++) {
            int ti = t - 3 + k;
            if (ti >= 0) acc = fmaf(cw[c * 4 + k], src[(size_t)ti * DPROJP], acc);
        }
        g_xbc[id] = acc / (1.f + expf(-acc));   // SiLU
    } else {
        int id = (blockIdx.x - CONVBLK) * 256 + threadIdx.x;
        int h  = id % NHEADS;
        int bt = id / NHEADS;
        float v  = g_zx[(size_t)bt * DPROJP + (DINNER + DINNER + 2 * DSTATE) + h] + dt_bias[h];
        float sp = (v > 20.f) ? v : log1pf(expf(v));
        g_dt[id] = sp;
        g_dA[id] = expf(-expf(A_log[h]) * sp);
    }
}

// ---------------- 3a) scan pass A: per-chunk local state U + decay P ---------
// grid = NBH*NCH (3072). 256 threads = 8 warps; warp wid owns 16 n's
// (n0 = wid*16); thread owns TWO p's: p_a = lane, p_b = lane+32.
// B loads: 4 uniform float4/warp/step (no cross-warp duplication of n).
// dA/dt staged in smem once per chunk (uniform LDS.64/step).
__global__ void __launch_bounds__(256) scanA_kernel() {
    __shared__ float2 sdAdt[QCH];

    int blk = blockIdx.x;
    int c  = blk & (NCH - 1);
    int bh = blk >> 5;
    int b = bh / NHEADS, h = bh % NHEADS;
    int tid = threadIdx.x;
    int wid = tid >> 5, lane = tid & 31;
    int n0 = wid * 16;
    int t0 = c * QCH;

    const float* base = g_xbc + (size_t)(b * LSEQ + t0) * CONVCH;
    const float* dAb  = g_dA + (b * LSEQ + t0) * NHEADS + h;
    const float* dtb  = g_dt + (b * LSEQ + t0) * NHEADS + h;

    if (tid < QCH) sdAdt[tid] = make_float2(dAb[tid * NHEADS], dtb[tid * NHEADS]);
    __syncthreads();

    u64 ha[8], hb[8];
    #pragma unroll
    for (int i = 0; i < 8; i++) { ha[i] = 0ull; hb[i] = 0ull; }

    #pragma unroll 2
    for (int tt = 0; tt < QCH; tt++) {
        const float* row = base + (size_t)tt * CONVCH;
        float2 ad = sdAdt[tt];
        float xa = row[h * HEADDIM + lane];
        float xb = row[h * HEADDIM + lane + 32];
        float dtxa = ad.y * xa, dtxb = ad.y * xb;
        u64 cdA2 = pk2(ad.x, ad.x);
        u64 da2  = pk2(dtxa, dtxa);
        u64 db2  = pk2(dtxb, dtxb);
        const float4* Bp = (const float4*)(row + DINNER + n0);
        #pragma unroll
        for (int j = 0; j < 4; j++) {
            float4 bv = Bp[j];                       // warp-uniform broadcast
            u64 b01 = pk2(bv.x, bv.y), b23 = pk2(bv.z, bv.w);
            ha[2*j]   = ffma2(cdA2, ha[2*j],   fmul2(da2, b01));
            ha[2*j+1] = ffma2(cdA2, ha[2*j+1], fmul2(da2, b23));
            hb[2*j]   = ffma2(cdA2, hb[2*j],   fmul2(db2, b01));
            hb[2*j+1] = ffma2(cdA2, hb[2*j+1], fmul2(db2, b23));
        }
    }

    float* Up = g_U + (size_t)blk * STATE_SZ;        // [n][p] layout
    #pragma unroll
    for (int k = 0; k < 8; k++) {
        int n = n0 + 2 * k;
        float lo, hi;
        up2(ha[k], lo, hi);
        Up[(size_t)n * HEADDIM + lane]            = lo;   // coalesced over lanes
        Up[(size_t)(n + 1) * HEADDIM + lane]      = hi;
        up2(hb[k], lo, hi);
        Up[(size_t)n * HEADDIM + lane + 32]       = lo;
        Up[(size_t)(n + 1) * HEADDIM + lane + 32] = hi;
    }
    if (tid == 0) {
        float Pacc = 1.f;
        for (int i = 0; i < QCH; i++) Pacc *= sdAdt[i].x;
        g_P[blk] = Pacc;
    }
}

// ---------------- 3b) scan pass B: sequential chunk-state chain --------------
__global__ void __launch_bounds__(256) scanB_kernel() {
    int bh = blockIdx.x >> 3, part = blockIdx.x & 7;
    int e0 = part * 1024 + threadIdx.x;
    float hcur[4] = {0.f, 0.f, 0.f, 0.f};
    for (int c = 0; c < NCH; c++) {
        size_t off = (size_t)(bh * NCH + c) * STATE_SZ + e0;
        float P = g_P[bh * NCH + c];
        #pragma unroll
        for (int k = 0; k < 4; k++) {
            g_hc[off + k * 256] = hcur[k];
            hcur[k] = fmaf(P, hcur[k], g_U[off + k * 256]);
        }
    }
}

// ---------------- 3c) scan pass C: replay chunk from true start, emit y ------
// Same mapping as scanA. Cross-warp y-reduction over the 8 n-groups via
// double-buffered sY[8][64]; warps 0/1 finalize (they hold x for their p's).
__global__ void __launch_bounds__(256) scanC_kernel(const float* __restrict__ Dv) {
    __shared__ float2 sdAdt[QCH];
    __shared__ float sY[2][8][64];

    int blk = blockIdx.x;
    int c  = blk & (NCH - 1);
    int bh = blk >> 5;
    int b = bh / NHEADS, h = bh % NHEADS;
    int tid = threadIdx.x;
    int wid = tid >> 5, lane = tid & 31;
    int n0 = wid * 16;
    int t0 = c * QCH;

    const float* base = g_xbc + (size_t)(b * LSEQ + t0) * CONVCH;
    const float* dAb  = g_dA + (b * LSEQ + t0) * NHEADS + h;
    const float* dtb  = g_dt + (b * LSEQ + t0) * NHEADS + h;
    float Dh = Dv[h];
    float* ybase = g_y + (size_t)(b * LSEQ + t0) * DINNER + h * HEADDIM;

    if (tid < QCH) sdAdt[tid] = make_float2(dAb[tid * NHEADS], dtb[tid * NHEADS]);
    __syncthreads();

    // load chunk start state ([n][p] layout, coalesced over lanes)
    const float* Hp = g_hc + (size_t)blk * STATE_SZ;
    u64 ha[8], hb[8];
    #pragma unroll
    for (int k = 0; k < 8; k++) {
        int n = n0 + 2 * k;
        ha[k] = pk2(Hp[(size_t)n * HEADDIM + lane],
                    Hp[(size_t)(n + 1) * HEADDIM + lane]);
        hb[k] = pk2(Hp[(size_t)n * HEADDIM + lane + 32],
                    Hp[(size_t)(n + 1) * HEADDIM + lane + 32]);
    }

    int buf = 0;
    for (int tt = 0; tt < QCH; tt++) {
        const float* row = base + (size_t)tt * CONVCH;
        float2 ad = sdAdt[tt];
        float xa = row[h * HEADDIM + lane];
        float xb = row[h * HEADDIM + lane + 32];
        float dtxa = ad.y * xa, dtxb = ad.y * xb;
        u64 cdA2 = pk2(ad.x, ad.x);
        u64 da2  = pk2(dtxa, dtxa);
        u64 db2  = pk2(dtxb, dtxb);
        const float4* Bp = (const float4*)(row + DINNER + n0);
        const float4* Cp = (const float4*)(row + DINNER + DSTATE + n0);
        u64 acc_a = 0ull, acc_b = 0ull;
        #pragma unroll
        for (int j = 0; j < 4; j++) {
            float4 bv = Bp[j];
            float4 cv = Cp[j];
            u64 b01 = pk2(bv.x, bv.y), b23 = pk2(bv.z, bv.w);
            u64 c01 = pk2(cv.x, cv.y), c23 = pk2(cv.z, cv.w);
            ha[2*j]   = ffma2(cdA2, ha[2*j],   fmul2(da2, b01));
            acc_a     = ffma2(ha[2*j],   c01, acc_a);
            ha[2*j+1] = ffma2(cdA2, ha[2*j+1], fmul2(da2, b23));
            acc_a     = ffma2(ha[2*j+1], c23, acc_a);
            hb[2*j]   = ffma2(cdA2, hb[2*j],   fmul2(db2, b01));
            acc_b     = ffma2(hb[2*j],   c01, acc_b);
            hb[2*j+1] = ffma2(cdA2, hb[2*j+1], fmul2(db2, b23));
            acc_b     = ffma2(hb[2*j+1], c23, acc_b);
        }
        float a0, a1; up2(acc_a, a0, a1);
        float b0, b1; up2(acc_b, b0, b1);
        sY[buf][wid][lane]      = a0 + a1;
        sY[buf][wid][lane + 32] = b0 + b1;
        __syncthreads();
        if (wid == 0) {
            float ys = 0.f;
            #pragma unroll
            for (int w = 0; w < 8; w++) ys += sY[buf][w][lane];
            ybase[(size_t)tt * DINNER + lane] = fmaf(Dh, xa, ys);
        } else if (wid == 1) {
            float ys = 0.f;
            #pragma unroll
            for (int w = 0; w < 8; w++) ys += sY[buf][w][lane + 32];
            ybase[(size_t)tt * DINNER + lane + 32] = fmaf(Dh, xb, ys);
        }
        buf ^= 1;
    }
}

// ---------------- 4) gate (y * silu(z)) + RMSNorm (fp16 output) ---------------
__global__ void __launch_bounds__(256) gate_kernel(const float* __restrict__ norm_w) {
    __shared__ float red[32];
    int row = blockIdx.x;
    const float* zr = g_zx + (size_t)row * DPROJP;
    const float* yr = g_y + (size_t)row * DINNER;
    __half* yo = g_yh + (size_t)row * DINNER;
    float gbuf[6], ss = 0.f;
    #pragma unroll
    for (int i = 0; i < 6; i++) {
        int c = threadIdx.x + i * 256;
        float z = zr[c];
        float y = yr[c];
        float gv = y * (z / (1.f + expf(-z)));
        gbuf[i] = gv;
        ss += gv * gv;
    }
    float tot = block_reduce_sum(ss, red);
    float inv = rsqrtf(tot / DINNER + EPSV);
    #pragma unroll
    for (int i = 0; i < 6; i++) {
        int c = threadIdx.x + i * 256;
        yo[c] = __float2half_rn(gbuf[i] * inv * norm_w[c]);
    }
}

// ---------------- launcher ----------------------------------------------------
extern "C" void kernel_launch(void* const* d_in, const int* in_sizes, int n_in,
                              void* d_out, int out_size) {
    const float* x       = (const float*)d_in[0];
    const float* ln_w    = (const float*)d_in[1];
    const float* ln_b    = (const float*)d_in[2];
    const float* W_in    = (const float*)d_in[3];
    const float* conv_w  = (const float*)d_in[4];
    const float* conv_b  = (const float*)d_in[5];
    const float* A_log   = (const float*)d_in[6];
    const float* Dv      = (const float*)d_in[7];
    const float* dt_bias = (const float*)d_in[8];
    const float* norm_w  = (const float*)d_in[9];
    const float* W_out   = (const float*)d_in[10];
    float* out = (float*)d_out;

    __half *puh, *pyh, *pwinh, *pwouth;
    float  *pzx;
    cudaGetSymbolAddress((void**)&puh,    g_uh);
    cudaGetSymbolAddress((void**)&pzx,    g_zx);
    cudaGetSymbolAddress((void**)&pyh,    g_yh);
    cudaGetSymbolAddress((void**)&pwinh,  g_winh);
    cudaGetSymbolAddress((void**)&pwouth, g_wouth);

    cudaFuncSetAttribute(gemm_fp16<false>, cudaFuncAttributeMaxDynamicSharedMemorySize, GEMM_SMEM);
    cudaFuncSetAttribute(gemm_fp16<true>,  cudaFuncAttributeMaxDynamicSharedMemorySize, GEMM_SMEM);

    // idx 0: LN + weight conversion (grid tail)
    lnfused_kernel<<<NBT + CVTB, 256>>>(x, ln_w, ln_b, W_in, W_out);

    // idx 1: GEMM1 [16384x768]@[768x3456]
    dim3 g1(DPROJP / 128, NBT / 128);
    gemm_fp16<false><<<g1, 256, GEMM_SMEM>>>(puh, pwinh, pzx, nullptr,
                                             DPROJP, DPROJP, DMODEL);

    // idx 2: conv + SiLU, dt/dA in tail
    convdt_kernel<<<CONVBLK + DTBLK, 256>>>(conv_w, conv_b, dt_bias, A_log);

    // idx 3: scan pass A (profiled slot)
    scanA_kernel<<<NBH * NCH, 256>>>();

    // idx 4: scan pass B (chunk-state chain)
    scanB_kernel<<<NBH * 8, 256>>>();

    // idx 5: scan pass C (emit y)
    scanC_kernel<<<NBH * NCH, 256>>>(Dv);

    // idx 6: gate + RMSNorm
    gate_kernel<<<NBT, 256>>>(norm_w);

    // idx 7: GEMM2 [16384x1536]@[1536x768] + x
    dim3 g2(DMODEL / 128, NBT / 128);
    gemm_fp16<true><<<g2, 256, GEMM_SMEM>>>(pyh, pwouth, out, x,
                                            DMODEL, DMODEL, DINNER);
}

// round 14
// speedup vs baseline: 5.2471x; 1.4181x over previous
#include <cuda_runtime.h>
#include <cuda_fp16.h>
#include <math.h>
#include <cstdint>
#include <mma.h>

using namespace nvcuda;

#define BSZ     4
#define LSEQ    4096
#define DMODEL  768
#define DSTATE  128
#define HEADDIM 64
#define DINNER  1536
#define NHEADS  24
#define DPROJ   3352       // logical in-proj width
#define DPROJP  3456       // padded to 27*128
#define CONVCH  1792       // 1536 + 2*128
#define EPSV    1e-5f
#define NBT     (BSZ*LSEQ) // 16384

#define QCH     128                 // scan chunk length
#define NCH     (LSEQ/QCH)          // 32 chunks
#define NBH     (BSZ*NHEADS)        // 96
#define STATE_SZ (HEADDIM*DSTATE)   // 8192 per (b,h)
#define STA     16                  // scanA staging sub-tile (steps)
#define STC     8                   // scanC staging sub-tile (steps)

#define WINSZ   (DMODEL*DPROJP)     // 2,654,208
#define WOUTSZ  (DINNER*DMODEL)     // 1,179,648
#define CVTB    ((WINSZ + WOUTSZ) / 1024)   // 3744 (exact)

typedef unsigned long long u64;

// ---------------- scratch (static device globals) ---------------------------
__device__ __half g_uh   [(size_t)NBT * DMODEL];    // LN output, fp16
__device__ float  g_zx   [(size_t)NBT * DPROJP];    // GEMM1 out, fp32
__device__ float  g_xbc  [(size_t)NBT * CONVCH];
__device__ float  g_y    [(size_t)NBT * DINNER];    // scan out, fp32
__device__ __half g_yh   [(size_t)NBT * DINNER];    // gated+normed, fp16
__device__ float  g_dA   [NBT * NHEADS];
__device__ float  g_dt   [NBT * NHEADS];
__device__ __half g_winh [(size_t)WINSZ];           // fp16, padded cols
__device__ __half g_wouth[(size_t)WOUTSZ];          // fp16
// chunked-scan scratch: layout [bh*NCH + c][n(128)][p(64)]
__device__ float  g_U    [(size_t)NBH * NCH * STATE_SZ];   // chunk local sums
__device__ float  g_hc   [(size_t)NBH * NCH * STATE_SZ];   // chunk start states
__device__ float  g_P    [NBH * NCH];                      // chunk decay products

// ---------------- helpers ----------------------------------------------------
__device__ __forceinline__ u64 pk2(float lo, float hi) {
    u64 d; asm("mov.b64 %0, {%1, %2};" : "=l"(d) : "f"(lo), "f"(hi)); return d;
}
__device__ __forceinline__ void up2(u64 v, float& lo, float& hi) {
    asm("mov.b64 {%0, %1}, %2;" : "=f"(lo), "=f"(hi) : "l"(v));
}
__device__ __forceinline__ u64 ffma2(u64 a, u64 b, u64 c) {
    u64 d; asm("fma.rn.f32x2 %0, %1, %2, %3;" : "=l"(d) : "l"(a), "l"(b), "l"(c)); return d;
}
__device__ __forceinline__ u64 fmul2(u64 a, u64 b) {
    u64 d; asm("mul.rn.f32x2 %0, %1, %2;" : "=l"(d) : "l"(a), "l"(b)); return d;
}
__device__ __forceinline__ unsigned smem_u32(const void* p) {
    return (unsigned)__cvta_generic_to_shared(p);
}
#define CP16(dst, src)  asm volatile("cp.async.cg.shared.global [%0], [%1], 16;" :: "r"(dst), "l"(src))
#define CP_COMMIT()     asm volatile("cp.async.commit_group;")
#define CP_WAIT(n)      asm volatile("cp.async.wait_group %0;" :: "n"(n))

__device__ __forceinline__ float block_reduce_sum(float v, float* red) {
    #pragma unroll
    for (int o = 16; o; o >>= 1) v += __shfl_down_sync(0xffffffffu, v, o);
    int lane = threadIdx.x & 31, wid = threadIdx.x >> 5;
    if (lane == 0) red[wid] = v;
    __syncthreads();
    int nw = blockDim.x >> 5;
    v = (threadIdx.x < nw) ? red[threadIdx.x] : 0.f;
    if (wid == 0) {
        #pragma unroll
        for (int o = 16; o; o >>= 1) v += __shfl_down_sync(0xffffffffu, v, o);
        if (lane == 0) red[0] = v;
    }
    __syncthreads();
    return red[0];
}

// ---------------- 0+1) LayerNorm (fp16 out) + weight cvt (grid tail) ---------
__global__ void __launch_bounds__(256) lnfused_kernel(const float* __restrict__ x,
                                                      const float* __restrict__ w,
                                                      const float* __restrict__ b,
                                                      const float* __restrict__ Wi,
                                                      const float* __restrict__ Wo) {
    if (blockIdx.x < NBT) {
        __shared__ float red[32];
        int row = blockIdx.x;
        const float* xr = x + (size_t)row * DMODEL;
        float v[3], s = 0.f, ss = 0.f;
        #pragma unroll
        for (int i = 0; i < 3; i++) {
            v[i] = xr[threadIdx.x + i * 256];
            s += v[i]; ss += v[i] * v[i];
        }
        float tot = block_reduce_sum(s, red);
        __syncthreads();
        float tot2 = block_reduce_sum(ss, red);
        float mu  = tot / DMODEL;
        float var = tot2 / DMODEL - mu * mu;
        float inv = rsqrtf(var + EPSV);
        __half* ur = g_uh + (size_t)row * DMODEL;
        #pragma unroll
        for (int i = 0; i < 3; i++) {
            int c = threadIdx.x + i * 256;
            ur[c] = __float2half_rn((v[i] - mu) * inv * w[c] + b[c]);
        }
    } else {
        int e0 = (blockIdx.x - NBT) * 1024 + threadIdx.x * 4;
        #pragma unroll
        for (int j = 0; j < 4; j++) {
            int e = e0 + j;
            if (e < WINSZ) {
                int r = e / DPROJP, c = e - r * DPROJP;
                g_winh[e] = (c < DPROJ)
                          ? __float2half_rn(Wi[(size_t)r * DPROJ + c])
                          : __half(0.f);
            } else {
                int i2 = e - WINSZ;
                g_wouth[i2] = __float2half_rn(Wo[i2]);
            }
        }
    }
}

// ---------------- FP16 wmma GEMM, 3-stage cp.async ring ----------------------
#define GSTG 3
#define ASTRH 40
#define BSTRH 136
#define A_ELEMH (128 * ASTRH)
#define B_ELEMH (32 * BSTRH)
#define STG_ELEMH (A_ELEMH + B_ELEMH)
#define GEMM_SMEM (GSTG * STG_ELEMH * 2)   // 56,832 B

template<bool RESID>
__global__ void __launch_bounds__(256, 2)
gemm_fp16(const __half* __restrict__ A, const __half* __restrict__ B,
          float* __restrict__ C, const float* __restrict__ R,
          int NP, int NB, int K) {
    extern __shared__ __half hsm[];
    __half* As = hsm;
    __half* Bs = hsm + GSTG * A_ELEMH;

    int tid  = threadIdx.x;
    int warp = tid >> 5, wm = warp >> 1, wn = warp & 1;
    int row0 = blockIdx.y * 128, col0 = blockIdx.x * 128;

    wmma::fragment<wmma::accumulator, 16, 16, 16, float> acc[2][4];
    #pragma unroll
    for (int i = 0; i < 2; i++)
        #pragma unroll
        for (int j = 0; j < 4; j++) wmma::fill_fragment(acc[i][j], 0.f);

    int a_r = tid >> 2, a_c = (tid & 3) * 8;
    int b_r = tid >> 4, b_c = (tid & 15) * 8;

    auto issue_stage = [&](int s, int k0) {
        __half* Ad = As + s * A_ELEMH;
        __half* Bd = Bs + s * B_ELEMH;
        #pragma unroll
        for (int u = 0; u < 2; u++) {
            int r = a_r + u * 64;
            CP16(smem_u32(Ad + r * ASTRH + a_c),
                 A + (size_t)(row0 + r) * K + k0 + a_c);
        }
        #pragma unroll
        for (int u = 0; u < 2; u++) {
            int r = b_r + u * 16;
            CP16(smem_u32(Bd + r * BSTRH + b_c),
                 B + (size_t)(k0 + r) * NB + col0 + b_c);
        }
    };

    int nk = K / 32;
    issue_stage(0, 0);  CP_COMMIT();
    issue_stage(1, 32); CP_COMMIT();

    for (int i = 0; i < nk; i++) {
        CP_WAIT(1);
        __syncthreads();
        if (i + 2 < nk) issue_stage((i + 2) % GSTG, (i + 2) * 32);
        CP_COMMIT();

        int s = i % GSTG;
        const __half* Ap = As + s * A_ELEMH;
        const __half* Bp = Bs + s * B_ELEMH;
        #pragma unroll
        for (int kk = 0; kk < 32; kk += 16) {
            wmma::fragment<wmma::matrix_a, 16, 16, 16, __half, wmma::row_major> af[2];
            #pragma unroll
            for (int a = 0; a < 2; a++)
                wmma::load_matrix_sync(af[a], Ap + (wm * 32 + a * 16) * ASTRH + kk, ASTRH);
            #pragma unroll
            for (int b2 = 0; b2 < 4; b2++) {
                wmma::fragment<wmma::matrix_b, 16, 16, 16, __half, wmma::row_major> bf;
                wmma::load_matrix_sync(bf, Bp + kk * BSTRH + wn * 64 + b2 * 16, BSTRH);
                wmma::mma_sync(acc[0][b2], af[0], bf, acc[0][b2]);
                wmma::mma_sync(acc[1][b2], af[1], bf, acc[1][b2]);
            }
        }
    }

    #pragma unroll
    for (int i = 0; i < 2; i++)
        #pragma unroll
        for (int j = 0; j < 4; j++) {
            int r = row0 + wm * 32 + i * 16;
            int c = col0 + wn * 64 + j * 16;
            float* Cp = C + (size_t)r * NP + c;
            if (RESID) {
                wmma::fragment<wmma::accumulator, 16, 16, 16, float> rf;
                wmma::load_matrix_sync(rf, R + (size_t)r * NP + c, NP, wmma::mem_row_major);
                #pragma unroll
                for (int e = 0; e < rf.num_elements; e++) acc[i][j].x[e] += rf.x[e];
            }
            wmma::store_matrix_sync(Cp, acc[i][j], NP, wmma::mem_row_major);
        }
}

// ---------------- 2) conv(K=4)+SiLU with dt/dA in grid tail -------------------
#define CONVBLK ((NBT * CONVCH) / 256)
#define DTBLK   ((NBT * NHEADS) / 256)
__global__ void __launch_bounds__(256) convdt_kernel(const float* __restrict__ cw,
                                                     const float* __restrict__ cb,
                                                     const float* __restrict__ dt_bias,
                                                     const float* __restrict__ A_log) {
    if (blockIdx.x < CONVBLK) {
        int id = blockIdx.x * 256 + threadIdx.x;
        int c  = id % CONVCH;
        int bt = id / CONVCH;
        int t  = bt % LSEQ;
        int b  = bt / LSEQ;
        const float* src = g_zx + (size_t)(b * LSEQ) * DPROJP + DINNER + c;
        float acc = cb[c];
        #pragma unroll
        for (int k = 0; k < 4; k++) {
            int ti = t - 3 + k;
            if (ti >= 0) acc = fmaf(cw[c * 4 + k], src[(size_t)ti * DPROJP], acc);
        }
        g_xbc[id] = acc / (1.f + expf(-acc));   // SiLU
    } else {
        int id = (blockIdx.x - CONVBLK) * 256 + threadIdx.x;
        int h  = id % NHEADS;
        int bt = id / NHEADS;
        float v  = g_zx[(size_t)bt * DPROJP + (DINNER + DINNER + 2 * DSTATE) + h] + dt_bias[h];
        float sp = (v > 20.f) ? v : log1pf(expf(v));
        g_dt[id] = sp;
        g_dA[id] = expf(-expf(A_log[h]) * sp);
    }
}

// ---------------- 3a) scan pass A: cp.async-staged chunk recurrence ----------
// grid = NBH*NCH (3072). 8 warps: warp owns 16 n (n0 = wid*16); thread owns
// p_a = lane, p_b = lane+32. B/x staged via double-buffered cp.async tiles of
// STA=16 steps; inner loop is pure LDS + f32x2 FMA.
__global__ void __launch_bounds__(256) scanA_kernel() {
    __shared__ float2 sdAdt[QCH];                 // 1 KB
    __shared__ float  sB[2][STA][DSTATE];         // 16 KB
    __shared__ float  sX[2][STA][HEADDIM];        // 8 KB

    int blk = blockIdx.x;
    int c  = blk & (NCH - 1);
    int bh = blk >> 5;
    int b = bh / NHEADS, h = bh % NHEADS;
    int tid = threadIdx.x;
    int wid = tid >> 5, lane = tid & 31;
    int n0 = wid * 16;
    int t0 = c * QCH;

    const float* base = g_xbc + (size_t)(b * LSEQ + t0) * CONVCH;
    const float* dAb  = g_dA + (b * LSEQ + t0) * NHEADS + h;
    const float* dtb  = g_dt + (b * LSEQ + t0) * NHEADS + h;

    if (tid < QCH) sdAdt[tid] = make_float2(dAb[tid * NHEADS], dtb[tid * NHEADS]);

    auto issue_tile = [&](int s, int tt0) {
        #pragma unroll
        for (int k = 0; k < 2; k++) {            // B: 512 float4
            int idx = tid + k * 256;
            int r = idx >> 5, q = (idx & 31) * 4;
            CP16(smem_u32(&sB[s][r][q]),
                 base + (size_t)(tt0 + r) * CONVCH + DINNER + q);
        }
        {                                        // X: 256 float4
            int r = tid >> 4, q = (tid & 15) * 4;
            CP16(smem_u32(&sX[s][r][q]),
                 base + (size_t)(tt0 + r) * CONVCH + h * HEADDIM + q);
        }
    };

    issue_tile(0, 0); CP_COMMIT();

    u64 ha[8], hb[8];
    #pragma unroll
    for (int i = 0; i < 8; i++) { ha[i] = 0ull; hb[i] = 0ull; }

    for (int it = 0; it < QCH / STA; it++) {
        CP_WAIT(0);
        __syncthreads();
        if (it + 1 < QCH / STA) issue_tile((it + 1) & 1, (it + 1) * STA);
        CP_COMMIT();
        int s = it & 1;
        #pragma unroll 4
        for (int r = 0; r < STA; r++) {
            float2 ad = sdAdt[it * STA + r];
            float xa = sX[s][r][lane];
            float xb = sX[s][r][lane + 32];
            float dtxa = ad.y * xa, dtxb = ad.y * xb;
            u64 cdA2 = pk2(ad.x, ad.x);
            u64 da2  = pk2(dtxa, dtxa);
            u64 db2  = pk2(dtxb, dtxb);
            const float4* Bp = (const float4*)&sB[s][r][n0];
            #pragma unroll
            for (int j = 0; j < 4; j++) {
                float4 bv = Bp[j];                   // warp-uniform LDS broadcast
                u64 b01 = pk2(bv.x, bv.y), b23 = pk2(bv.z, bv.w);
                ha[2*j]   = ffma2(cdA2, ha[2*j],   fmul2(da2, b01));
                ha[2*j+1] = ffma2(cdA2, ha[2*j+1], fmul2(da2, b23));
                hb[2*j]   = ffma2(cdA2, hb[2*j],   fmul2(db2, b01));
                hb[2*j+1] = ffma2(cdA2, hb[2*j+1], fmul2(db2, b23));
            }
        }
    }

    float* Up = g_U + (size_t)blk * STATE_SZ;        // [n][p] layout
    #pragma unroll
    for (int k = 0; k < 8; k++) {
        int n = n0 + 2 * k;
        float lo, hi;
        up2(ha[k], lo, hi);
        Up[(size_t)n * HEADDIM + lane]            = lo;
        Up[(size_t)(n + 1) * HEADDIM + lane]      = hi;
        up2(hb[k], lo, hi);
        Up[(size_t)n * HEADDIM + lane + 32]       = lo;
        Up[(size_t)(n + 1) * HEADDIM + lane + 32] = hi;
    }
    if (tid == 0) {
        float Pacc = 1.f;
        for (int i = 0; i < QCH; i++) Pacc *= sdAdt[i].x;
        g_P[blk] = Pacc;
    }
}

// ---------------- 3b) scan pass B: sequential chunk-state chain --------------
__global__ void __launch_bounds__(256) scanB_kernel() {
    int bh = blockIdx.x >> 3, part = blockIdx.x & 7;
    int e0 = part * 1024 + threadIdx.x;
    float hcur[4] = {0.f, 0.f, 0.f, 0.f};
    for (int c = 0; c < NCH; c++) {
        size_t off = (size_t)(bh * NCH + c) * STATE_SZ + e0;
        float P = g_P[bh * NCH + c];
        #pragma unroll
        for (int k = 0; k < 4; k++) {
            g_hc[off + k * 256] = hcur[k];
            hcur[k] = fmaf(P, hcur[k], g_U[off + k * 256]);
        }
    }
}

// ---------------- 3c) scan pass C: staged replay, batched y-reduction --------
// Same mapping as scanA. B+C staged together (contiguous in g_xbc rows) in
// STC=8-step double-buffered tiles; y partials collected in sYt and reduced
// once per tile (2 barriers per 8 steps instead of 8).
__global__ void __launch_bounds__(256) scanC_kernel(const float* __restrict__ Dv) {
    __shared__ float2 sdAdt[QCH];                 // 1 KB
    __shared__ float  sBC[2][STC][2 * DSTATE];    // 16 KB ([0..127]=B,[128..255]=C)
    __shared__ float  sX [2][STC][HEADDIM];       // 4 KB
    __shared__ float  sYt[STC][8][HEADDIM];       // 16 KB

    int blk = blockIdx.x;
    int c  = blk & (NCH - 1);
    int bh = blk >> 5;
    int b = bh / NHEADS, h = bh % NHEADS;
    int tid = threadIdx.x;
    int wid = tid >> 5, lane = tid & 31;
    int n0 = wid * 16;
    int t0 = c * QCH;

    const float* base = g_xbc + (size_t)(b * LSEQ + t0) * CONVCH;
    const float* dAb  = g_dA + (b * LSEQ + t0) * NHEADS + h;
    const float* dtb  = g_dt + (b * LSEQ + t0) * NHEADS + h;
    float Dh = Dv[h];
    float* ybase = g_y + (size_t)(b * LSEQ + t0) * DINNER + h * HEADDIM;

    if (tid < QCH) sdAdt[tid] = make_float2(dAb[tid * NHEADS], dtb[tid * NHEADS]);

    auto issue_tile = [&](int s, int tt0) {
        #pragma unroll
        for (int k = 0; k < 2; k++) {            // B+C: 512 float4
            int idx = tid + k * 256;
            int r = idx >> 6, q = (idx & 63) * 4;
            CP16(smem_u32(&sBC[s][r][q]),
                 base + (size_t)(tt0 + r) * CONVCH + DINNER + q);
        }
        if (tid < 128) {                         // X: 128 float4
            int r = tid >> 4, q = (tid & 15) * 4;
            CP16(smem_u32(&sX[s][r][q]),
                 base + (size_t)(tt0 + r) * CONVCH + h * HEADDIM + q);
        }
    };

    issue_tile(0, 0); CP_COMMIT();

    // load chunk start state ([n][p] layout, coalesced over lanes)
    const float* Hp = g_hc + (size_t)blk * STATE_SZ;
    u64 ha[8], hb[8];
    #pragma unroll
    for (int k = 0; k < 8; k++) {
        int n = n0 + 2 * k;
        ha[k] = pk2(Hp[(size_t)n * HEADDIM + lane],
                    Hp[(size_t)(n + 1) * HEADDIM + lane]);
        hb[k] = pk2(Hp[(size_t)n * HEADDIM + lane + 32],
                    Hp[(size_t)(n + 1) * HEADDIM + lane + 32]);
    }

    for (int it = 0; it < QCH / STC; it++) {
        CP_WAIT(0);
        __syncthreads();                          // tile ready + sYt reads done
        if (it + 1 < QCH / STC) issue_tile((it + 1) & 1, (it + 1) * STC);
        CP_COMMIT();
        int s = it & 1;
        #pragma unroll
        for (int r = 0; r < STC; r++) {
            float2 ad = sdAdt[it * STC + r];
            float xa = sX[s][r][lane];
            float xb = sX[s][r][lane + 32];
            float dtxa = ad.y * xa, dtxb = ad.y * xb;
            u64 cdA2 = pk2(ad.x, ad.x);
            u64 da2  = pk2(dtxa, dtxa);
            u64 db2  = pk2(dtxb, dtxb);
            const float4* Bp = (const float4*)&sBC[s][r][n0];
            const float4* Cp = (const float4*)&sBC[s][r][DSTATE + n0];
            u64 acc_a = 0ull, acc_b = 0ull;
            #pragma unroll
            for (int j = 0; j < 4; j++) {
                float4 bv = Bp[j];
                float4 cv = Cp[j];
                u64 b01 = pk2(bv.x, bv.y), b23 = pk2(bv.z, bv.w);
                u64 c01 = pk2(cv.x, cv.y), c23 = pk2(cv.z, cv.w);
                ha[2*j]   = ffma2(cdA2, ha[2*j],   fmul2(da2, b01));
                acc_a     = ffma2(ha[2*j],   c01, acc_a);
                ha[2*j+1] = ffma2(cdA2, ha[2*j+1], fmul2(da2, b23));
                acc_a     = ffma2(ha[2*j+1], c23, acc_a);
                hb[2*j]   = ffma2(cdA2, hb[2*j],   fmul2(db2, b01));
                acc_b     = ffma2(hb[2*j],   c01, acc_b);
                hb[2*j+1] = ffma2(cdA2, hb[2*j+1], fmul2(db2, b23));
                acc_b     = ffma2(hb[2*j+1], c23, acc_b);
            }
            float a0, a1; up2(acc_a, a0, a1);
            float b0, b1; up2(acc_b, b0, b1);
            sYt[r][wid][lane]      = a0 + a1;
            sYt[r][wid][lane + 32] = b0 + b1;
        }
        __syncthreads();                          // sYt writes visible
        // batched reduction: 512 outputs (8 steps x 64 p), 2 per thread
        #pragma unroll
        for (int k = 0; k < 2; k++) {
            int o = tid + k * 256;
            int t = o >> 6, p = o & 63;
            float ys = 0.f;
            #pragma unroll
            for (int w = 0; w < 8; w++) ys += sYt[t][w][p];
            float xv = sX[s][t][p];
            ybase[(size_t)(it * STC + t) * DINNER + p] = fmaf(Dh, xv, ys);
        }
    }
}

// ---------------- 4) gate (y * silu(z)) + RMSNorm (fp16 output) ---------------
__global__ void __launch_bounds__(256) gate_kernel(const float* __restrict__ norm_w) {
    __shared__ float red[32];
    int row = blockIdx.x;
    const float* zr = g_zx + (size_t)row * DPROJP;
    const float* yr = g_y + (size_t)row * DINNER;
    __half* yo = g_yh + (size_t)row * DINNER;
    float gbuf[6], ss = 0.f;
    #pragma unroll
    for (int i = 0; i < 6; i++) {
        int c = threadIdx.x + i * 256;
        float z = zr[c];
        float y = yr[c];
        float gv = y * (z / (1.f + expf(-z)));
        gbuf[i] = gv;
        ss += gv * gv;
    }
    float tot = block_reduce_sum(ss, red);
    float inv = rsqrtf(tot / DINNER + EPSV);
    #pragma unroll
    for (int i = 0; i < 6; i++) {
        int c = threadIdx.x + i * 256;
        yo[c] = __float2half_rn(gbuf[i] * inv * norm_w[c]);
    }
}

// ---------------- launcher ----------------------------------------------------
extern "C" void kernel_launch(void* const* d_in, const int* in_sizes, int n_in,
                              void* d_out, int out_size) {
    const float* x       = (const float*)d_in[0];
    const float* ln_w    = (const float*)d_in[1];
    const float* ln_b    = (const float*)d_in[2];
    const float* W_in    = (const float*)d_in[3];
    const float* conv_w  = (const float*)d_in[4];
    const float* conv_b  = (const float*)d_in[5];
    const float* A_log   = (const float*)d_in[6];
    const float* Dv      = (const float*)d_in[7];
    const float* dt_bias = (const float*)d_in[8];
    const float* norm_w  = (const float*)d_in[9];
    const float* W_out   = (const float*)d_in[10];
    float* out = (float*)d_out;

    __half *puh, *pyh, *pwinh, *pwouth;
    float  *pzx;
    cudaGetSymbolAddress((void**)&puh,    g_uh);
    cudaGetSymbolAddress((void**)&pzx,    g_zx);
    cudaGetSymbolAddress((void**)&pyh,    g_yh);
    cudaGetSymbolAddress((void**)&pwinh,  g_winh);
    cudaGetSymbolAddress((void**)&pwouth, g_wouth);

    cudaFuncSetAttribute(gemm_fp16<false>, cudaFuncAttributeMaxDynamicSharedMemorySize, GEMM_SMEM);
    cudaFuncSetAttribute(gemm_fp16<true>,  cudaFuncAttributeMaxDynamicSharedMemorySize, GEMM_SMEM);

    // idx 0: LN + weight conversion (grid tail)
    lnfused_kernel<<<NBT + CVTB, 256>>>(x, ln_w, ln_b, W_in, W_out);

    // idx 1: GEMM1 [16384x768]@[768x3456]
    dim3 g1(DPROJP / 128, NBT / 128);
    gemm_fp16<false><<<g1, 256, GEMM_SMEM>>>(puh, pwinh, pzx, nullptr,
                                             DPROJP, DPROJP, DMODEL);

    // idx 2: conv + SiLU, dt/dA in tail
    convdt_kernel<<<CONVBLK + DTBLK, 256>>>(conv_w, conv_b, dt_bias, A_log);

    // idx 3: scan pass A (profiled slot)
    scanA_kernel<<<NBH * NCH, 256>>>();

    // idx 4: scan pass B (chunk-state chain)
    scanB_kernel<<<NBH * 8, 256>>>();

    // idx 5: scan pass C (emit y)
    scanC_kernel<<<NBH * NCH, 256>>>(Dv);

    // idx 6: gate + RMSNorm
    gate_kernel<<<NBT, 256>>>(norm_w);

    // idx 7: GEMM2 [16384x1536]@[1536x768] + x
    dim3 g2(DMODEL / 128, NBT / 128);
    gemm_fp16<true><<<g2, 256, GEMM_SMEM>>>(pyh, pwouth, out, x,
                                            DMODEL, DMODEL, DINNER);
}

// round 15
// speedup vs baseline: 5.6595x; 1.0786x over previous
#include <cuda_runtime.h>
#include <cuda_fp16.h>
#include <math.h>
#include <cstdint>
#include <mma.h>

using namespace nvcuda;

#define BSZ     4
#define LSEQ    4096
#define DMODEL  768
#define DSTATE  128
#define HEADDIM 64
#define DINNER  1536
#define NHEADS  24
#define DPROJ   3352       // logical in-proj width
#define DPROJP  3456       // padded to 27*128
#define CONVCH  1792       // 1536 + 2*128
#define EPSV    1e-5f
#define NBT     (BSZ*LSEQ) // 16384

#define QCH     128                 // scan chunk length
#define NCH     (LSEQ/QCH)          // 32 chunks
#define NBH     (BSZ*NHEADS)        // 96
#define STATE_SZ (HEADDIM*DSTATE)   // 8192 per (b,h)
#define STC     8                   // scanC staging sub-tile (steps)

#define WINSZ   (DMODEL*DPROJP)     // 2,654,208
#define WOUTSZ  (DINNER*DMODEL)     // 1,179,648
#define CVTB    ((WINSZ + WOUTSZ) / 1024)   // 3744 (exact)

// scanAg smem geometry
#define BWLD    136                 // half stride of (w*B) tile row
#define XLD     72                  // half stride of X tile row
#define SCANA_SMEM (128*BWLD*2 + 128*XLD*2 + 128*4)   // 53,760 B

typedef unsigned long long u64;

// ---------------- scratch (static device globals) ---------------------------
__device__ __half g_uh   [(size_t)NBT * DMODEL];    // LN output, fp16
__device__ float  g_zx   [(size_t)NBT * DPROJP];    // GEMM1 out, fp32
__device__ float  g_xbc  [(size_t)NBT * CONVCH];
__device__ float  g_y    [(size_t)NBT * DINNER];    // scan out, fp32
__device__ __half g_yh   [(size_t)NBT * DINNER];    // gated+normed, fp16
__device__ float  g_dA   [NBT * NHEADS];
__device__ float  g_dt   [NBT * NHEADS];
__device__ __half g_winh [(size_t)WINSZ];           // fp16, padded cols
__device__ __half g_wouth[(size_t)WOUTSZ];          // fp16
// chunked-scan scratch: layout [bh*NCH + c][n(128)][p(64)]
__device__ float  g_U    [(size_t)NBH * NCH * STATE_SZ];   // chunk local sums
__device__ float  g_hc   [(size_t)NBH * NCH * STATE_SZ];   // chunk start states
__device__ float  g_P    [NBH * NCH];                      // chunk decay products

// ---------------- helpers ----------------------------------------------------
__device__ __forceinline__ u64 pk2(float lo, float hi) {
    u64 d; asm("mov.b64 %0, {%1, %2};" : "=l"(d) : "f"(lo), "f"(hi)); return d;
}
__device__ __forceinline__ void up2(u64 v, float& lo, float& hi) {
    asm("mov.b64 {%0, %1}, %2;" : "=f"(lo), "=f"(hi) : "l"(v));
}
__device__ __forceinline__ u64 ffma2(u64 a, u64 b, u64 c) {
    u64 d; asm("fma.rn.f32x2 %0, %1, %2, %3;" : "=l"(d) : "l"(a), "l"(b), "l"(c)); return d;
}
__device__ __forceinline__ u64 fmul2(u64 a, u64 b) {
    u64 d; asm("mul.rn.f32x2 %0, %1, %2;" : "=l"(d) : "l"(a), "l"(b)); return d;
}
__device__ __forceinline__ unsigned smem_u32(const void* p) {
    return (unsigned)__cvta_generic_to_shared(p);
}
#define CP16(dst, src)  asm volatile("cp.async.cg.shared.global [%0], [%1], 16;" :: "r"(dst), "l"(src))
#define CP_COMMIT()     asm volatile("cp.async.commit_group;")
#define CP_WAIT(n)      asm volatile("cp.async.wait_group %0;" :: "n"(n))

__device__ __forceinline__ float block_reduce_sum(float v, float* red) {
    #pragma unroll
    for (int o = 16; o; o >>= 1) v += __shfl_down_sync(0xffffffffu, v, o);
    int lane = threadIdx.x & 31, wid = threadIdx.x >> 5;
    if (lane == 0) red[wid] = v;
    __syncthreads();
    int nw = blockDim.x >> 5;
    v = (threadIdx.x < nw) ? red[threadIdx.x] : 0.f;
    if (wid == 0) {
        #pragma unroll
        for (int o = 16; o; o >>= 1) v += __shfl_down_sync(0xffffffffu, v, o);
        if (lane == 0) red[0] = v;
    }
    __syncthreads();
    return red[0];
}

// ---------------- 0+1) LayerNorm (fp16 out) + weight cvt (grid tail) ---------
__global__ void __launch_bounds__(256) lnfused_kernel(const float* __restrict__ x,
                                                      const float* __restrict__ w,
                                                      const float* __restrict__ b,
                                                      const float* __restrict__ Wi,
                                                      const float* __restrict__ Wo) {
    if (blockIdx.x < NBT) {
        __shared__ float red[32];
        int row = blockIdx.x;
        const float* xr = x + (size_t)row * DMODEL;
        float v[3], s = 0.f, ss = 0.f;
        #pragma unroll
        for (int i = 0; i < 3; i++) {
            v[i] = xr[threadIdx.x + i * 256];
            s += v[i]; ss += v[i] * v[i];
        }
        float tot = block_reduce_sum(s, red);
        __syncthreads();
        float tot2 = block_reduce_sum(ss, red);
        float mu  = tot / DMODEL;
        float var = tot2 / DMODEL - mu * mu;
        float inv = rsqrtf(var + EPSV);
        __half* ur = g_uh + (size_t)row * DMODEL;
        #pragma unroll
        for (int i = 0; i < 3; i++) {
            int c = threadIdx.x + i * 256;
            ur[c] = __float2half_rn((v[i] - mu) * inv * w[c] + b[c]);
        }
    } else {
        int e0 = (blockIdx.x - NBT) * 1024 + threadIdx.x * 4;
        #pragma unroll
        for (int j = 0; j < 4; j++) {
            int e = e0 + j;
            if (e < WINSZ) {
                int r = e / DPROJP, c = e - r * DPROJP;
                g_winh[e] = (c < DPROJ)
                          ? __float2half_rn(Wi[(size_t)r * DPROJ + c])
                          : __half(0.f);
            } else {
                int i2 = e - WINSZ;
                g_wouth[i2] = __float2half_rn(Wo[i2]);
            }
        }
    }
}

// ---------------- FP16 wmma GEMM, 3-stage cp.async ring ----------------------
#define GSTG 3
#define ASTRH 40
#define BSTRH 136
#define A_ELEMH (128 * ASTRH)
#define B_ELEMH (32 * BSTRH)
#define STG_ELEMH (A_ELEMH + B_ELEMH)
#define GEMM_SMEM (GSTG * STG_ELEMH * 2)   // 56,832 B

template<bool RESID>
__global__ void __launch_bounds__(256, 2)
gemm_fp16(const __half* __restrict__ A, const __half* __restrict__ B,
          float* __restrict__ C, const float* __restrict__ R,
          int NP, int NB, int K) {
    extern __shared__ __half hsm[];
    __half* As = hsm;
    __half* Bs = hsm + GSTG * A_ELEMH;

    int tid  = threadIdx.x;
    int warp = tid >> 5, wm = warp >> 1, wn = warp & 1;
    int row0 = blockIdx.y * 128, col0 = blockIdx.x * 128;

    wmma::fragment<wmma::accumulator, 16, 16, 16, float> acc[2][4];
    #pragma unroll
    for (int i = 0; i < 2; i++)
        #pragma unroll
        for (int j = 0; j < 4; j++) wmma::fill_fragment(acc[i][j], 0.f);

    int a_r = tid >> 2, a_c = (tid & 3) * 8;
    int b_r = tid >> 4, b_c = (tid & 15) * 8;

    auto issue_stage = [&](int s, int k0) {
        __half* Ad = As + s * A_ELEMH;
        __half* Bd = Bs + s * B_ELEMH;
        #pragma unroll
        for (int u = 0; u < 2; u++) {
            int r = a_r + u * 64;
            CP16(smem_u32(Ad + r * ASTRH + a_c),
                 A + (size_t)(row0 + r) * K + k0 + a_c);
        }
        #pragma unroll
        for (int u = 0; u < 2; u++) {
            int r = b_r + u * 16;
            CP16(smem_u32(Bd + r * BSTRH + b_c),
                 B + (size_t)(k0 + r) * NB + col0 + b_c);
        }
    };

    int nk = K / 32;
    issue_stage(0, 0);  CP_COMMIT();
    issue_stage(1, 32); CP_COMMIT();

    for (int i = 0; i < nk; i++) {
        CP_WAIT(1);
        __syncthreads();
        if (i + 2 < nk) issue_stage((i + 2) % GSTG, (i + 2) * 32);
        CP_COMMIT();

        int s = i % GSTG;
        const __half* Ap = As + s * A_ELEMH;
        const __half* Bp = Bs + s * B_ELEMH;
        #pragma unroll
        for (int kk = 0; kk < 32; kk += 16) {
            wmma::fragment<wmma::matrix_a, 16, 16, 16, __half, wmma::row_major> af[2];
            #pragma unroll
            for (int a = 0; a < 2; a++)
                wmma::load_matrix_sync(af[a], Ap + (wm * 32 + a * 16) * ASTRH + kk, ASTRH);
            #pragma unroll
            for (int b2 = 0; b2 < 4; b2++) {
                wmma::fragment<wmma::matrix_b, 16, 16, 16, __half, wmma::row_major> bf;
                wmma::load_matrix_sync(bf, Bp + kk * BSTRH + wn * 64 + b2 * 16, BSTRH);
                wmma::mma_sync(acc[0][b2], af[0], bf, acc[0][b2]);
                wmma::mma_sync(acc[1][b2], af[1], bf, acc[1][b2]);
            }
        }
    }

    #pragma unroll
    for (int i = 0; i < 2; i++)
        #pragma unroll
        for (int j = 0; j < 4; j++) {
            int r = row0 + wm * 32 + i * 16;
            int c = col0 + wn * 64 + j * 16;
            float* Cp = C + (size_t)r * NP + c;
            if (RESID) {
                wmma::fragment<wmma::accumulator, 16, 16, 16, float> rf;
                wmma::load_matrix_sync(rf, R + (size_t)r * NP + c, NP, wmma::mem_row_major);
                #pragma unroll
                for (int e = 0; e < rf.num_elements; e++) acc[i][j].x[e] += rf.x[e];
            }
            wmma::store_matrix_sync(Cp, acc[i][j], NP, wmma::mem_row_major);
        }
}

// ---------------- 2) conv(K=4)+SiLU with dt/dA in grid tail -------------------
#define CONVBLK ((NBT * CONVCH) / 256)
#define DTBLK   ((NBT * NHEADS) / 256)
__global__ void __launch_bounds__(256) convdt_kernel(const float* __restrict__ cw,
                                                     const float* __restrict__ cb,
                                                     const float* __restrict__ dt_bias,
                                                     const float* __restrict__ A_log) {
    if (blockIdx.x < CONVBLK) {
        int id = blockIdx.x * 256 + threadIdx.x;
        int c  = id % CONVCH;
        int bt = id / CONVCH;
        int t  = bt % LSEQ;
        int b  = bt / LSEQ;
        const float* src = g_zx + (size_t)(b * LSEQ) * DPROJP + DINNER + c;
        float acc = cb[c];
        #pragma unroll
        for (int k = 0; k < 4; k++) {
            int ti = t - 3 + k;
            if (ti >= 0) acc = fmaf(cw[c * 4 + k], src[(size_t)ti * DPROJP], acc);
        }
        g_xbc[id] = acc / (1.f + expf(-acc));   // SiLU
    } else {
        int id = (blockIdx.x - CONVBLK) * 256 + threadIdx.x;
        int h  = id % NHEADS;
        int bt = id / NHEADS;
        float v  = g_zx[(size_t)bt * DPROJP + (DINNER + DINNER + 2 * DSTATE) + h] + dt_bias[h];
        float sp = (v > 20.f) ? v : log1pf(expf(v));
        g_dt[id] = sp;
        g_dA[id] = expf(-expf(A_log[h]) * sp);
    }
}

// ---------------- 3a) scan pass A as tensor-core GEMM -------------------------
// U[n][p] = sum_s w_s * B_s[n] * x_s[p], w_s = dt_s * prod_{u>s} dA_u.
// Suffix products computed by warp 0 (underflow -> 0 is numerically correct).
// grid = NBH*NCH (3072), 256 threads = 8 warps in 4(m) x 2(n) wmma grid.
__global__ void __launch_bounds__(256) scanAg_kernel() {
    extern __shared__ char dyn[];
    __half* sBw = (__half*)dyn;                         // [128][BWLD]
    __half* sXh = sBw + 128 * BWLD;                     // [128][XLD]
    float*  sW  = (float*)(sXh + 128 * XLD);            // [128]

    int blk = blockIdx.x;
    int c  = blk & (NCH - 1);
    int bh = blk >> 5;
    int b = bh / NHEADS, h = bh % NHEADS;
    int tid = threadIdx.x;
    int wid = tid >> 5, lane = tid & 31;
    int t0 = c * QCH;

    const float* base = g_xbc + (size_t)(b * LSEQ + t0) * CONVCH;
    const float* dAb  = g_dA + (b * LSEQ + t0) * NHEADS + h;
    const float* dtb  = g_dt + (b * LSEQ + t0) * NHEADS + h;

    // warp 0: suffix decay products + weights + P
    if (wid == 0) {
        float seg[4];
        float q = 1.f;
        #pragma unroll
        for (int k = 0; k < 4; k++) {
            seg[k] = dAb[(lane * 4 + k) * NHEADS];
            q *= seg[k];
        }
        float pr = q;   // will become prod over lanes >= lane
        #pragma unroll
        for (int o = 1; o < 32; o <<= 1) {
            float v = __shfl_down_sync(0xffffffffu, pr, o);
            if (lane + o < 32) pr *= v;
        }
        float Sl = __shfl_down_sync(0xffffffffu, pr, 1);   // prod over lanes > lane
        if (lane == 31) Sl = 1.f;
        float Ptot = __shfl_sync(0xffffffffu, pr, 0);
        if (lane == 0) g_P[blk] = Ptot;
        float run = Sl;                                    // prod dA_u, u > s
        #pragma unroll
        for (int k = 3; k >= 0; k--) {
            int s = lane * 4 + k;
            sW[s] = dtb[s * NHEADS] * run;
            run *= seg[k];
        }
    }
    __syncthreads();

    // stage (w*B) and x as fp16
    {
        int s0 = tid >> 1;
        int nh = (tid & 1) * 64;
        float wv = sW[s0];
        const float* Brow = base + (size_t)s0 * CONVCH + DINNER + nh;
        __half* dst = sBw + s0 * BWLD + nh;
        #pragma unroll
        for (int j = 0; j < 16; j++) {
            float4 v = *(const float4*)(Brow + j * 4);
            *(__half2*)(dst + j * 4)     = __floats2half2_rn(v.x * wv, v.y * wv);
            *(__half2*)(dst + j * 4 + 2) = __floats2half2_rn(v.z * wv, v.w * wv);
        }
        int p0 = (tid & 1) * 32;
        const float* Xrow = base + (size_t)s0 * CONVCH + h * HEADDIM + p0;
        __half* xdst = sXh + s0 * XLD + p0;
        #pragma unroll
        for (int j = 0; j < 8; j++) {
            float4 v = *(const float4*)(Xrow + j * 4);
            *(__half2*)(xdst + j * 4)     = __floats2half2_rn(v.x, v.y);
            *(__half2*)(xdst + j * 4 + 2) = __floats2half2_rn(v.z, v.w);
        }
    }
    __syncthreads();

    // wmma: U = (wB)^T @ X  (m=128 n-dim, n=64 p-dim, k=128 steps)
    int wm = wid >> 1, wn = wid & 1;
    wmma::fragment<wmma::accumulator, 16, 16, 16, float> acc[2][2];
    #pragma unroll
    for (int i = 0; i < 2; i++)
        #pragma unroll
        for (int j = 0; j < 2; j++) wmma::fill_fragment(acc[i][j], 0.f);

    #pragma unroll
    for (int kk = 0; kk < QCH; kk += 16) {
        wmma::fragment<wmma::matrix_a, 16, 16, 16, __half, wmma::col_major> af[2];
        wmma::fragment<wmma::matrix_b, 16, 16, 16, __half, wmma::row_major> bf[2];
        #pragma unroll
        for (int i = 0; i < 2; i++)
            wmma::load_matrix_sync(af[i], sBw + kk * BWLD + wm * 32 + i * 16, BWLD);
        #pragma unroll
        for (int j = 0; j < 2; j++)
            wmma::load_matrix_sync(bf[j], sXh + kk * XLD + wn * 32 + j * 16, XLD);
        #pragma unroll
        for (int i = 0; i < 2; i++)
            #pragma unroll
            for (int j = 0; j < 2; j++)
                wmma::mma_sync(acc[i][j], af[i], bf[j], acc[i][j]);
    }

    float* Up = g_U + (size_t)blk * STATE_SZ;           // [n][p], ld = 64
    #pragma unroll
    for (int i = 0; i < 2; i++)
        #pragma unroll
        for (int j = 0; j < 2; j++)
            wmma::store_matrix_sync(Up + (wm * 32 + i * 16) * HEADDIM + wn * 32 + j * 16,
                                    acc[i][j], HEADDIM, wmma::mem_row_major);
}

// ---------------- 3b) scan pass B: sequential chunk-state chain --------------
__global__ void __launch_bounds__(256) scanB_kernel() {
    int bh = blockIdx.x >> 3, part = blockIdx.x & 7;
    int e0 = part * 1024 + threadIdx.x;
    float hcur[4] = {0.f, 0.f, 0.f, 0.f};
    for (int c = 0; c < NCH; c++) {
        size_t off = (size_t)(bh * NCH + c) * STATE_SZ + e0;
        float P = g_P[bh * NCH + c];
        #pragma unroll
        for (int k = 0; k < 4; k++) {
            g_hc[off + k * 256] = hcur[k];
            hcur[k] = fmaf(P, hcur[k], g_U[off + k * 256]);
        }
    }
}

// ---------------- 3c) scan pass C: staged replay, batched y-reduction --------
__global__ void __launch_bounds__(256) scanC_kernel(const float* __restrict__ Dv) {
    __shared__ float2 sdAdt[QCH];                 // 1 KB
    __shared__ float  sBC[2][STC][2 * DSTATE];    // 16 KB ([0..127]=B,[128..255]=C)
    __shared__ float  sX [2][STC][HEADDIM];       // 4 KB
    __shared__ float  sYt[STC][8][HEADDIM];       // 16 KB

    int blk = blockIdx.x;
    int c  = blk & (NCH - 1);
    int bh = blk >> 5;
    int b = bh / NHEADS, h = bh % NHEADS;
    int tid = threadIdx.x;
    int wid = tid >> 5, lane = tid & 31;
    int n0 = wid * 16;
    int t0 = c * QCH;

    const float* base = g_xbc + (size_t)(b * LSEQ + t0) * CONVCH;
    const float* dAb  = g_dA + (b * LSEQ + t0) * NHEADS + h;
    const float* dtb  = g_dt + (b * LSEQ + t0) * NHEADS + h;
    float Dh = Dv[h];
    float* ybase = g_y + (size_t)(b * LSEQ + t0) * DINNER + h * HEADDIM;

    if (tid < QCH) sdAdt[tid] = make_float2(dAb[tid * NHEADS], dtb[tid * NHEADS]);

    auto issue_tile = [&](int s, int tt0) {
        #pragma unroll
        for (int k = 0; k < 2; k++) {            // B+C: 512 float4
            int idx = tid + k * 256;
            int r = idx >> 6, q = (idx & 63) * 4;
            CP16(smem_u32(&sBC[s][r][q]),
                 base + (size_t)(tt0 + r) * CONVCH + DINNER + q);
        }
        if (tid < 128) {                         // X: 128 float4
            int r = tid >> 4, q = (tid & 15) * 4;
            CP16(smem_u32(&sX[s][r][q]),
                 base + (size_t)(tt0 + r) * CONVCH + h * HEADDIM + q);
        }
    };

    issue_tile(0, 0); CP_COMMIT();

    // load chunk start state ([n][p] layout, coalesced over lanes)
    const float* Hp = g_hc + (size_t)blk * STATE_SZ;
    u64 ha[8], hb[8];
    #pragma unroll
    for (int k = 0; k < 8; k++) {
        int n = n0 + 2 * k;
        ha[k] = pk2(Hp[(size_t)n * HEADDIM + lane],
                    Hp[(size_t)(n + 1) * HEADDIM + lane]);
        hb[k] = pk2(Hp[(size_t)n * HEADDIM + lane + 32],
                    Hp[(size_t)(n + 1) * HEADDIM + lane + 32]);
    }

    for (int it = 0; it < QCH / STC; it++) {
        CP_WAIT(0);
        __syncthreads();                          // tile ready + sYt reads done
        if (it + 1 < QCH / STC) issue_tile((it + 1) & 1, (it + 1) * STC);
        CP_COMMIT();
        int s = it & 1;
        #pragma unroll
        for (int r = 0; r < STC; r++) {
            float2 ad = sdAdt[it * STC + r];
            float xa = sX[s][r][lane];
            float xb = sX[s][r][lane + 32];
            float dtxa = ad.y * xa, dtxb = ad.y * xb;
            u64 cdA2 = pk2(ad.x, ad.x);
            u64 da2  = pk2(dtxa, dtxa);
            u64 db2  = pk2(dtxb, dtxb);
            const float4* Bp = (const float4*)&sBC[s][r][n0];
            const float4* Cp = (const float4*)&sBC[s][r][DSTATE + n0];
            u64 acc_a = 0ull, acc_b = 0ull;
            #pragma unroll
            for (int j = 0; j < 4; j++) {
                float4 bv = Bp[j];
                float4 cv = Cp[j];
                u64 b01 = pk2(bv.x, bv.y), b23 = pk2(bv.z, bv.w);
                u64 c01 = pk2(cv.x, cv.y), c23 = pk2(cv.z, cv.w);
                ha[2*j]   = ffma2(cdA2, ha[2*j],   fmul2(da2, b01));
                acc_a     = ffma2(ha[2*j],   c01, acc_a);
                ha[2*j+1] = ffma2(cdA2, ha[2*j+1], fmul2(da2, b23));
                acc_a     = ffma2(ha[2*j+1], c23, acc_a);
                hb[2*j]   = ffma2(cdA2, hb[2*j],   fmul2(db2, b01));
                acc_b     = ffma2(hb[2*j],   c01, acc_b);
                hb[2*j+1] = ffma2(cdA2, hb[2*j+1], fmul2(db2, b23));
                acc_b     = ffma2(hb[2*j+1], c23, acc_b);
            }
            float a0, a1; up2(acc_a, a0, a1);
            float b0, b1; up2(acc_b, b0, b1);
            sYt[r][wid][lane]      = a0 + a1;
            sYt[r][wid][lane + 32] = b0 + b1;
        }
        __syncthreads();                          // sYt writes visible
        // batched reduction: 512 outputs (8 steps x 64 p), 2 per thread
        #pragma unroll
        for (int k = 0; k < 2; k++) {
            int o = tid + k * 256;
            int t = o >> 6, p = o & 63;
            float ys = 0.f;
            #pragma unroll
            for (int w = 0; w < 8; w++) ys += sYt[t][w][p];
            float xv = sX[s][t][p];
            ybase[(size_t)(it * STC + t) * DINNER + p] = fmaf(Dh, xv, ys);
        }
    }
}

// ---------------- 4) gate (y * silu(z)) + RMSNorm (fp16 output) ---------------
__global__ void __launch_bounds__(256) gate_kernel(const float* __restrict__ norm_w) {
    __shared__ float red[32];
    int row = blockIdx.x;
    const float* zr = g_zx + (size_t)row * DPROJP;
    const float* yr = g_y + (size_t)row * DINNER;
    __half* yo = g_yh + (size_t)row * DINNER;
    float gbuf[6], ss = 0.f;
    #pragma unroll
    for (int i = 0; i < 6; i++) {
        int c = threadIdx.x + i * 256;
        float z = zr[c];
        float y = yr[c];
        float gv = y * (z / (1.f + expf(-z)));
        gbuf[i] = gv;
        ss += gv * gv;
    }
    float tot = block_reduce_sum(ss, red);
    float inv = rsqrtf(tot / DINNER + EPSV);
    #pragma unroll
    for (int i = 0; i < 6; i++) {
        int c = threadIdx.x + i * 256;
        yo[c] = __float2half_rn(gbuf[i] * inv * norm_w[c]);
    }
}

// ---------------- launcher ----------------------------------------------------
extern "C" void kernel_launch(void* const* d_in, const int* in_sizes, int n_in,
                              void* d_out, int out_size) {
    const float* x       = (const float*)d_in[0];
    const float* ln_w    = (const float*)d_in[1];
    const float* ln_b    = (const float*)d_in[2];
    const float* W_in    = (const float*)d_in[3];
    const float* conv_w  = (const float*)d_in[4];
    const float* conv_b  = (const float*)d_in[5];
    const float* A_log   = (const float*)d_in[6];
    const float* Dv      = (const float*)d_in[7];
    const float* dt_bias = (const float*)d_in[8];
    const float* norm_w  = (const float*)d_in[9];
    const float* W_out   = (const float*)d_in[10];
    float* out = (float*)d_out;

    __half *puh, *pyh, *pwinh, *pwouth;
    float  *pzx;
    cudaGetSymbolAddress((void**)&puh,    g_uh);
    cudaGetSymbolAddress((void**)&pzx,    g_zx);
    cudaGetSymbolAddress((void**)&pyh,    g_yh);
    cudaGetSymbolAddress((void**)&pwinh,  g_winh);
    cudaGetSymbolAddress((void**)&pwouth, g_wouth);

    cudaFuncSetAttribute(gemm_fp16<false>, cudaFuncAttributeMaxDynamicSharedMemorySize, GEMM_SMEM);
    cudaFuncSetAttribute(gemm_fp16<true>,  cudaFuncAttributeMaxDynamicSharedMemorySize, GEMM_SMEM);
    cudaFuncSetAttribute(scanAg_kernel,    cudaFuncAttributeMaxDynamicSharedMemorySize, SCANA_SMEM);

    // idx 0: LN + weight conversion (grid tail)
    lnfused_kernel<<<NBT + CVTB, 256>>>(x, ln_w, ln_b, W_in, W_out);

    // idx 1: GEMM1 [16384x768]@[768x3456]
    dim3 g1(DPROJP / 128, NBT / 128);
    gemm_fp16<false><<<g1, 256, GEMM_SMEM>>>(puh, pwinh, pzx, nullptr,
                                             DPROJP, DPROJP, DMODEL);

    // idx 2: conv + SiLU, dt/dA in tail
    convdt_kernel<<<CONVBLK + DTBLK, 256>>>(conv_w, conv_b, dt_bias, A_log);

    // idx 3: scan pass A as tensor GEMM (profiled slot)
    scanAg_kernel<<<NBH * NCH, 256, SCANA_SMEM>>>();

    // idx 4: scan pass B (chunk-state chain)
    scanB_kernel<<<NBH * 8, 256>>>();

    // idx 5: scan pass C (emit y)
    scanC_kernel<<<NBH * NCH, 256>>>(Dv);

    // idx 6: gate + RMSNorm
    gate_kernel<<<NBT, 256>>>(norm_w);

    // idx 7: GEMM2 [16384x1536]@[1536x768] + x
    dim3 g2(DMODEL / 128, NBT / 128);
    gemm_fp16<true><<<g2, 256, GEMM_SMEM>>>(pyh, pwouth, out, x,
                                            DMODEL, DMODEL, DINNER);
}